// round 10
// baseline (speedup 1.0000x reference)
#include <cuda_runtime.h>
#include <cuda_bf16.h>
#include <cstdint>
#include <math.h>

// Problem constants
#define B_  2
#define S_  2048
#define D_  1024
#define H_  16
#define DK_ 64
#define M_  (B_*S_)   // 4096

typedef __nv_bfloat16 bf16;

// Scratch (allocation-free rule: __device__ globals), all hi/lo bf16 planes
__device__ bf16 g_Ah[(size_t)M_*D_], g_Al[(size_t)M_*D_];   // split input (reused q/k/v)
__device__ bf16 g_Wh[(size_t)D_*D_], g_Wl[(size_t)D_*D_];   // split weight (reused)
__device__ bf16 g_Qh[(size_t)M_*D_], g_Ql[(size_t)M_*D_];   // [B,H,S,DK]
__device__ bf16 g_Kh[(size_t)M_*D_], g_Kl[(size_t)M_*D_];
__device__ bf16 g_Vh[(size_t)M_*D_], g_Vl[(size_t)M_*D_];
__device__ bf16 g_Ch[(size_t)M_*D_], g_Cl[(size_t)M_*D_];   // context [B,S,D]

// ---------------------------------------------------------------------------
// Helpers
// ---------------------------------------------------------------------------
__device__ __forceinline__ void ldm_x4(uint32_t* r, uint32_t addr) {
    asm volatile("ldmatrix.sync.aligned.m8n8.x4.shared.b16 {%0,%1,%2,%3}, [%4];"
        : "=r"(r[0]), "=r"(r[1]), "=r"(r[2]), "=r"(r[3]) : "r"(addr));
}
__device__ __forceinline__ void ldm_x4_t(uint32_t* r, uint32_t addr) {
    asm volatile("ldmatrix.sync.aligned.m8n8.x4.trans.shared.b16 {%0,%1,%2,%3}, [%4];"
        : "=r"(r[0]), "=r"(r[1]), "=r"(r[2]), "=r"(r[3]) : "r"(addr));
}
__device__ __forceinline__ void mma_bf16(float* c, const uint32_t* a, const uint32_t* b) {
    asm volatile("mma.sync.aligned.m16n8k16.row.col.f32.bf16.bf16.f32 "
        "{%0,%1,%2,%3}, {%4,%5,%6,%7}, {%8,%9}, {%0,%1,%2,%3};"
        : "+f"(c[0]), "+f"(c[1]), "+f"(c[2]), "+f"(c[3])
        : "r"(a[0]), "r"(a[1]), "r"(a[2]), "r"(a[3]), "r"(b[0]), "r"(b[1]));
}
__device__ __forceinline__ uint32_t pack_hi2(float x, float y) {
    __nv_bfloat162 t(__float2bfloat16_rn(x), __float2bfloat16_rn(y));
    return *(uint32_t*)&t;
}
__device__ __forceinline__ uint32_t pack_lo2(float x, float y) {
    bf16 hx = __float2bfloat16_rn(x);
    bf16 hy = __float2bfloat16_rn(y);
    __nv_bfloat162 t(__float2bfloat16_rn(x - __bfloat162float(hx)),
                     __float2bfloat16_rn(y - __bfloat162float(hy)));
    return *(uint32_t*)&t;
}
__device__ __forceinline__ void cp16(uint32_t saddr, const void* g) {
    asm volatile("cp.async.cg.shared.global [%0], [%1], 16;" :: "r"(saddr), "l"(g));
}

// ---------------------------------------------------------------------------
// Split fp32 -> hi/lo bf16 planes (two arrays per launch)
// ---------------------------------------------------------------------------
__global__ void split_kernel(const float4* __restrict__ in1, uint2* __restrict__ h1,
                             uint2* __restrict__ l1, int n1q,
                             const float4* __restrict__ in2, uint2* __restrict__ h2,
                             uint2* __restrict__ l2, int n2q)
{
    int i = blockIdx.x * blockDim.x + threadIdx.x;
    const float4* in; uint2 *oh, *ol; int idx;
    if (i < n1q) { in = in1; oh = h1; ol = l1; idx = i; }
    else { idx = i - n1q; if (idx >= n2q) return; in = in2; oh = h2; ol = l2; }
    float4 v = in[idx];
    uint2 ph, pl;
    ph.x = pack_hi2(v.x, v.y); ph.y = pack_hi2(v.z, v.w);
    pl.x = pack_lo2(v.x, v.y); pl.y = pack_lo2(v.z, v.w);
    oh[idx] = ph; ol[idx] = pl;
}

// ---------------------------------------------------------------------------
// Pure-bf16 projection GEMM, cp.async double-buffered.
// out = A @ W^T + bias  (A = Ah+Al, W = Wh+Wl, 3-MMA emulated fp32)
// CTA 128x128, BK=32, 8 warps (2x4, warp tile 64x32), 2 CTAs/SM.
// ---------------------------------------------------------------------------
#define LDK 40
#define PLB  (128 * LDK * 2)        // plane bytes
#define STGB (4 * PLB)              // stage bytes (Ah,Al,Wh,Wl)
#define PROJ_SMEM (2 * STGB)        // 81,920 B

__global__ __launch_bounds__(256, 2) void proj_mma(
    const bf16* __restrict__ Ah, const bf16* __restrict__ Al,
    const bf16* __restrict__ Wh, const bf16* __restrict__ Wl,
    const float* __restrict__ bias,
    float* __restrict__ outF, bf16* __restrict__ outH, bf16* __restrict__ outL,
    int headSplit)
{
    extern __shared__ char smem_raw[];
    uint32_t smem_b = (uint32_t)__cvta_generic_to_shared(smem_raw);

    const int tid  = threadIdx.x;
    const int lane = tid & 31;
    const int wrp  = tid >> 5;
    const int wr = wrp >> 2;
    const int wc = wrp & 3;
    const int bm = blockIdx.y * 128;
    const int bn = blockIdx.x * 128;

    const int lrow = tid >> 1;
    const int lseg = (tid & 1) * 16;
    const bf16* gAh = Ah + (size_t)(bm + lrow) * D_ + lseg;
    const bf16* gAl = Al + (size_t)(bm + lrow) * D_ + lseg;
    const bf16* gWh = Wh + (size_t)(bn + lrow) * D_ + lseg;
    const bf16* gWl = Wl + (size_t)(bn + lrow) * D_ + lseg;
    const uint32_t sdst = smem_b + (uint32_t)(lrow * LDK + lseg) * 2u;

    float acc[4][4][4];
    #pragma unroll
    for (int mt = 0; mt < 4; mt++)
        #pragma unroll
        for (int nt = 0; nt < 4; nt++)
            #pragma unroll
            for (int r = 0; r < 4; r++) acc[mt][nt][r] = 0.f;

    const int a_r = lane & 15;
    const int a_k = (lane >> 4) * 8;
    const int b_r = (lane & 7) + ((lane >> 4) << 3);
    const int b_k = ((lane >> 3) & 1) * 8;

    // issue loads for a stage
    auto issue = [&](int stage, int k0) {
        uint32_t sb = sdst + stage * STGB;
        cp16(sb,               gAh + k0);
        cp16(sb + 16,          gAh + k0 + 8);
        cp16(sb + PLB,         gAl + k0);
        cp16(sb + PLB + 16,    gAl + k0 + 8);
        cp16(sb + 2*PLB,       gWh + k0);
        cp16(sb + 2*PLB + 16,  gWh + k0 + 8);
        cp16(sb + 3*PLB,       gWl + k0);
        cp16(sb + 3*PLB + 16,  gWl + k0 + 8);
        asm volatile("cp.async.commit_group;");
    };

    issue(0, 0);

    for (int c = 0; c < D_ / 32; c++) {
        if (c < D_ / 32 - 1) issue((c + 1) & 1, (c + 1) * 32);
        if (c < D_ / 32 - 1) asm volatile("cp.async.wait_group 1;");
        else                 asm volatile("cp.async.wait_group 0;");
        __syncthreads();

        uint32_t sAh_b = smem_b + (c & 1) * STGB;
        uint32_t sAl_b = sAh_b + PLB;
        uint32_t sWh_b = sAh_b + 2 * PLB;
        uint32_t sWl_b = sAh_b + 3 * PLB;

        #pragma unroll
        for (int ks = 0; ks < 2; ks++) {
            const int k0 = ks * 16;
            uint32_t afh[4][4], afl[4][4];
            #pragma unroll
            for (int mt = 0; mt < 4; mt++) {
                int m0 = wr * 64 + mt * 16;
                uint32_t off = (uint32_t)((m0 + a_r) * LDK + k0 + a_k) * 2u;
                ldm_x4(afh[mt], sAh_b + off);
                ldm_x4(afl[mt], sAl_b + off);
            }
            uint32_t bfh[4][2], bfl[4][2];
            #pragma unroll
            for (int np = 0; np < 2; np++) {
                int n0 = wc * 32 + np * 16;
                uint32_t off = (uint32_t)((n0 + b_r) * LDK + k0 + b_k) * 2u;
                uint32_t th[4], tl[4];
                ldm_x4(th, sWh_b + off);
                ldm_x4(tl, sWl_b + off);
                bfh[2*np][0]   = th[0]; bfh[2*np][1]   = th[1];
                bfh[2*np+1][0] = th[2]; bfh[2*np+1][1] = th[3];
                bfl[2*np][0]   = tl[0]; bfl[2*np][1]   = tl[1];
                bfl[2*np+1][0] = tl[2]; bfl[2*np+1][1] = tl[3];
            }
            #pragma unroll
            for (int mt = 0; mt < 4; mt++)
                #pragma unroll
                for (int nt = 0; nt < 4; nt++) {
                    mma_bf16(acc[mt][nt], afh[mt], bfh[nt]);
                    mma_bf16(acc[mt][nt], afl[mt], bfh[nt]);
                    mma_bf16(acc[mt][nt], afh[mt], bfl[nt]);
                }
        }
        __syncthreads();
    }

    // Epilogue
    const int g  = lane >> 2;
    const int i4 = lane & 3;
    #pragma unroll
    for (int mt = 0; mt < 4; mt++) {
        #pragma unroll
        for (int nt = 0; nt < 4; nt++) {
            int m = bm + wr * 64 + mt * 16 + g;
            int n = bn + wc * 32 + nt * 8 + i4 * 2;
            float b0 = bias[n], b1 = bias[n + 1];
            #pragma unroll
            for (int hf = 0; hf < 2; hf++) {
                int mm = m + hf * 8;
                float v0 = acc[mt][nt][hf * 2 + 0] + b0;
                float v1 = acc[mt][nt][hf * 2 + 1] + b1;
                if (headSplit) {
                    int bb = mm >> 11;
                    int s  = mm & (S_ - 1);
                    int h  = n >> 6;
                    int dk = n & (DK_ - 1);
                    size_t off = ((size_t)((bb * H_ + h) * S_ + s)) * DK_ + dk;
                    *(uint32_t*)(outH + off) = pack_hi2(v0, v1);
                    *(uint32_t*)(outL + off) = pack_lo2(v0, v1);
                } else {
                    *(float2*)(outF + (size_t)mm * D_ + n) = make_float2(v0, v1);
                }
            }
        }
    }
}

// ---------------------------------------------------------------------------
// Flash-attention on tensor cores, all operands pre-split bf16.
// CTA: 128 q-rows per (b,h). 8 warps x 16 rows, warp-local softmax,
// P in registers (C-frag == A-frag). 82.9 KB SMEM, 2 CTAs/SM.
// ---------------------------------------------------------------------------
#define LQ 72
#define ATTN_SMEM ((128*LQ + 64*LQ + 64*LQ) * 2 * 2 + 128*LQ)   // 82,944 B

__global__ __launch_bounds__(256, 2) void attn_mma(const int* __restrict__ mask)
{
    extern __shared__ char smem_raw[];
    bf16* Qh = (bf16*)smem_raw;
    bf16* Ql = Qh + 128 * LQ;
    bf16* Kh = Ql + 128 * LQ;
    bf16* Kl = Kh + 64 * LQ;
    bf16* Vh = Kl + 64 * LQ;
    bf16* Vl = Vh + 64 * LQ;
    uint8_t* Ms = (uint8_t*)(Vl + 64 * LQ);

    const int tid  = threadIdx.x;
    const int lane = tid & 31;
    const int warp = tid >> 5;
    const int b = blockIdx.z, h = blockIdx.y;
    const int q0 = blockIdx.x * 128;

    const size_t bh = ((size_t)(b * H_ + h)) * S_ * DK_;
    const bf16* Qhg = g_Qh + bh; const bf16* Qlg = g_Ql + bh;
    const bf16* Khg = g_Kh + bh; const bf16* Klg = g_Kl + bh;
    const bf16* Vhg = g_Vh + bh; const bf16* Vlg = g_Vl + bh;
    const int*  mb  = mask + (size_t)b * S_ * S_;

    uint32_t Qh_b = (uint32_t)__cvta_generic_to_shared(Qh);
    uint32_t Ql_b = (uint32_t)__cvta_generic_to_shared(Ql);
    uint32_t Kh_b = (uint32_t)__cvta_generic_to_shared(Kh);
    uint32_t Kl_b = (uint32_t)__cvta_generic_to_shared(Kl);
    uint32_t Vh_b = (uint32_t)__cvta_generic_to_shared(Vh);
    uint32_t Vl_b = (uint32_t)__cvta_generic_to_shared(Vl);

    // Load Q tile (row = tid>>1, 32-col half) — straight bf16 copies
    {
        int row = tid >> 1, seg = (tid & 1) * 32;
        const uint4* sh = (const uint4*)(Qhg + (size_t)(q0 + row) * DK_ + seg);
        const uint4* sl = (const uint4*)(Qlg + (size_t)(q0 + row) * DK_ + seg);
        uint4* dh = (uint4*)(Qh + row * LQ + seg);
        uint4* dl = (uint4*)(Ql + row * LQ + seg);
        #pragma unroll
        for (int u = 0; u < 4; u++) { dh[u] = sh[u]; dl[u] = sl[u]; }
    }

    float m_i[2] = { -INFINITY, -INFINITY };
    float l_i[2] = { 0.f, 0.f };
    float o[8][4];
    #pragma unroll
    for (int nt = 0; nt < 8; nt++)
        #pragma unroll
        for (int r = 0; r < 4; r++) o[nt][r] = 0.f;

    const int a_r = lane & 15;
    const int a_k = (lane >> 4) * 8;
    const int b_r = (lane & 7) + ((lane >> 4) << 3);
    const int b_k = ((lane >> 3) & 1) * 8;
    const int t_r = (lane & 7) + (((lane >> 3) & 1) << 3);
    const int t_c = (lane >> 4) * 8;

    for (int k0 = 0; k0 < S_; k0 += 64) {
        __syncthreads();

        // K/V tile copy (row = tid>>2, 16-col quarter)
        {
            int row = tid >> 2, seg = (tid & 3) * 16;
            size_t go = (size_t)(k0 + row) * DK_ + seg;
            int so = row * LQ + seg;
            #pragma unroll
            for (int u = 0; u < 2; u++) {
                ((uint4*)(Kh + so))[u] = ((const uint4*)(Khg + go))[u];
                ((uint4*)(Kl + so))[u] = ((const uint4*)(Klg + go))[u];
                ((uint4*)(Vh + so))[u] = ((const uint4*)(Vhg + go))[u];
                ((uint4*)(Vl + so))[u] = ((const uint4*)(Vlg + go))[u];
            }
        }
        // mask tile -> bytes
        {
            int row = tid >> 1, seg = (tid & 1) * 32;
            const int* mrow = mb + (size_t)(q0 + row) * S_ + k0 + seg;
            #pragma unroll
            for (int u = 0; u < 8; u++) {
                int4 m4 = *(const int4*)(mrow + u * 4);
                uchar4 cc;
                cc.x = (unsigned char)m4.x; cc.y = (unsigned char)m4.y;
                cc.z = (unsigned char)m4.z; cc.w = (unsigned char)m4.w;
                *(uchar4*)(Ms + row * LQ + seg + u * 4) = cc;
            }
        }
        __syncthreads();

        // ---- S = Q @ K^T ----
        float s[8][4];
        #pragma unroll
        for (int nt = 0; nt < 8; nt++)
            #pragma unroll
            for (int r = 0; r < 4; r++) s[nt][r] = 0.f;

        #pragma unroll
        for (int kt = 0; kt < 4; kt++) {
            uint32_t ah[4], al[4];
            uint32_t aoff = (uint32_t)((warp * 16 + a_r) * LQ + kt * 16 + a_k) * 2u;
            ldm_x4(ah, Qh_b + aoff);
            ldm_x4(al, Ql_b + aoff);
            #pragma unroll
            for (int nc = 0; nc < 4; nc++) {
                uint32_t bhf[4], blf[4];
                uint32_t boff = (uint32_t)((nc * 16 + b_r) * LQ + kt * 16 + b_k) * 2u;
                ldm_x4(bhf, Kh_b + boff);
                ldm_x4(blf, Kl_b + boff);
                mma_bf16(s[2*nc],   ah, &bhf[0]);
                mma_bf16(s[2*nc],   al, &bhf[0]);
                mma_bf16(s[2*nc],   ah, &blf[0]);
                mma_bf16(s[2*nc+1], ah, &bhf[2]);
                mma_bf16(s[2*nc+1], al, &bhf[2]);
                mma_bf16(s[2*nc+1], ah, &blf[2]);
            }
        }

        // ---- mask + online softmax ----
        const int grow0 = warp * 16 + (lane >> 2);
        const int cb = (lane & 3) * 2;
        #pragma unroll
        for (int r = 0; r < 2; r++) {
            int grow = grow0 + r * 8;
            float tmax = -INFINITY;
            #pragma unroll
            for (int nt = 0; nt < 8; nt++) {
                uint8_t mk0 = Ms[grow * LQ + nt * 8 + cb];
                uint8_t mk1 = Ms[grow * LQ + nt * 8 + cb + 1];
                float v0 = mk0 ? s[nt][r*2+0] * 0.125f : -1e9f;
                float v1 = mk1 ? s[nt][r*2+1] * 0.125f : -1e9f;
                s[nt][r*2+0] = v0; s[nt][r*2+1] = v1;
                tmax = fmaxf(tmax, fmaxf(v0, v1));
            }
            tmax = fmaxf(tmax, __shfl_xor_sync(0xffffffffu, tmax, 1));
            tmax = fmaxf(tmax, __shfl_xor_sync(0xffffffffu, tmax, 2));
            float mnew = fmaxf(m_i[r], tmax);
            float esc = __expf(m_i[r] - mnew);
            float rs = 0.f;
            #pragma unroll
            for (int nt = 0; nt < 8; nt++) {
                float p0 = __expf(s[nt][r*2+0] - mnew);
                float p1 = __expf(s[nt][r*2+1] - mnew);
                s[nt][r*2+0] = p0; s[nt][r*2+1] = p1;
                rs += p0 + p1;
            }
            rs += __shfl_xor_sync(0xffffffffu, rs, 1);
            rs += __shfl_xor_sync(0xffffffffu, rs, 2);
            l_i[r] = l_i[r] * esc + rs;
            m_i[r] = mnew;
            #pragma unroll
            for (int nt = 0; nt < 8; nt++) {
                o[nt][r*2+0] *= esc;
                o[nt][r*2+1] *= esc;
            }
        }

        // P C-frag -> A-frag packs (hi/lo)
        uint32_t pfh[4][4], pfl[4][4];
        #pragma unroll
        for (int kt = 0; kt < 4; kt++) {
            pfh[kt][0] = pack_hi2(s[2*kt][0],   s[2*kt][1]);
            pfh[kt][1] = pack_hi2(s[2*kt][2],   s[2*kt][3]);
            pfh[kt][2] = pack_hi2(s[2*kt+1][0], s[2*kt+1][1]);
            pfh[kt][3] = pack_hi2(s[2*kt+1][2], s[2*kt+1][3]);
            pfl[kt][0] = pack_lo2(s[2*kt][0],   s[2*kt][1]);
            pfl[kt][1] = pack_lo2(s[2*kt][2],   s[2*kt][3]);
            pfl[kt][2] = pack_lo2(s[2*kt+1][0], s[2*kt+1][1]);
            pfl[kt][3] = pack_lo2(s[2*kt+1][2], s[2*kt+1][3]);
        }

        // ---- O += P @ V ----
        #pragma unroll
        for (int kt = 0; kt < 4; kt++) {
            #pragma unroll
            for (int nd = 0; nd < 4; nd++) {
                uint32_t vh_[4], vl_[4];
                uint32_t voff = (uint32_t)((kt * 16 + t_r) * LQ + nd * 16 + t_c) * 2u;
                ldm_x4_t(vh_, Vh_b + voff);
                ldm_x4_t(vl_, Vl_b + voff);
                mma_bf16(o[2*nd],   pfh[kt], &vh_[0]);
                mma_bf16(o[2*nd],   pfl[kt], &vh_[0]);
                mma_bf16(o[2*nd],   pfh[kt], &vl_[0]);
                mma_bf16(o[2*nd+1], pfh[kt], &vh_[2]);
                mma_bf16(o[2*nd+1], pfl[kt], &vh_[2]);
                mma_bf16(o[2*nd+1], pfh[kt], &vl_[2]);
            }
        }
    }

    // Epilogue: normalize, write context hi/lo bf16 planes [B,S,D]
    #pragma unroll
    for (int r = 0; r < 2; r++) {
        int q = q0 + warp * 16 + (lane >> 2) + r * 8;
        float inv = 1.f / l_i[r];
        #pragma unroll
        for (int nt = 0; nt < 8; nt++) {
            float v0 = o[nt][r*2+0] * inv;
            float v1 = o[nt][r*2+1] * inv;
            size_t off = ((size_t)(b * S_ + q)) * D_ + h * DK_ + nt * 8 + (lane & 3) * 2;
            *(uint32_t*)(g_Ch + off) = pack_hi2(v0, v1);
            *(uint32_t*)(g_Cl + off) = pack_lo2(v0, v1);
        }
    }
}

// ---------------------------------------------------------------------------
// Launch
// ---------------------------------------------------------------------------
extern "C" void kernel_launch(void* const* d_in, const int* in_sizes, int n_in,
                              void* d_out, int out_size)
{
    const float* input_q = (const float*)d_in[0];
    const float* input_k = (const float*)d_in[1];
    const float* input_v = (const float*)d_in[2];
    const int*   mask    = (const int*)  d_in[3];
    const float* Wq = (const float*)d_in[4];
    const float* bq = (const float*)d_in[5];
    const float* Wk = (const float*)d_in[6];
    const float* bk = (const float*)d_in[7];
    const float* Wv = (const float*)d_in[8];
    const float* bv = (const float*)d_in[9];
    const float* Wo = (const float*)d_in[10];
    const float* bo = (const float*)d_in[11];
    float* out = (float*)d_out;

    bf16 *ah, *al, *wh, *wl, *qh, *ql, *kh, *kl, *vh, *vl, *ch, *cl;
    cudaGetSymbolAddress((void**)&ah, g_Ah); cudaGetSymbolAddress((void**)&al, g_Al);
    cudaGetSymbolAddress((void**)&wh, g_Wh); cudaGetSymbolAddress((void**)&wl, g_Wl);
    cudaGetSymbolAddress((void**)&qh, g_Qh); cudaGetSymbolAddress((void**)&ql, g_Ql);
    cudaGetSymbolAddress((void**)&kh, g_Kh); cudaGetSymbolAddress((void**)&kl, g_Kl);
    cudaGetSymbolAddress((void**)&vh, g_Vh); cudaGetSymbolAddress((void**)&vl, g_Vl);
    cudaGetSymbolAddress((void**)&ch, g_Ch); cudaGetSymbolAddress((void**)&cl, g_Cl);

    cudaFuncSetAttribute(proj_mma,
                         cudaFuncAttributeMaxDynamicSharedMemorySize, PROJ_SMEM);
    cudaFuncSetAttribute(attn_mma,
                         cudaFuncAttributeMaxDynamicSharedMemorySize, ATTN_SMEM);

    const int N1Q = M_ * D_ / 4;   // input quads
    const int N2Q = D_ * D_ / 4;   // weight quads
    const int SPLIT_BLK = (N1Q + N2Q + 255) / 256;
    dim3 pgrid(D_ / 128, M_ / 128);   // (8, 32)
    dim3 agrid(S_ / 128, H_, B_);     // (16, 16, 2)

    // Q
    split_kernel<<<SPLIT_BLK, 256>>>((const float4*)input_q, (uint2*)ah, (uint2*)al, N1Q,
                                     (const float4*)Wq, (uint2*)wh, (uint2*)wl, N2Q);
    proj_mma<<<pgrid, 256, PROJ_SMEM>>>(ah, al, wh, wl, bq, nullptr, qh, ql, 1);
    // K
    split_kernel<<<SPLIT_BLK, 256>>>((const float4*)input_k, (uint2*)ah, (uint2*)al, N1Q,
                                     (const float4*)Wk, (uint2*)wh, (uint2*)wl, N2Q);
    proj_mma<<<pgrid, 256, PROJ_SMEM>>>(ah, al, wh, wl, bk, nullptr, kh, kl, 1);
    // V
    split_kernel<<<SPLIT_BLK, 256>>>((const float4*)input_v, (uint2*)ah, (uint2*)al, N1Q,
                                     (const float4*)Wv, (uint2*)wh, (uint2*)wl, N2Q);
    proj_mma<<<pgrid, 256, PROJ_SMEM>>>(ah, al, wh, wl, bv, nullptr, vh, vl, 1);
    // attention
    attn_mma<<<agrid, 256, ATTN_SMEM>>>(mask);
    // output projection
    split_kernel<<<(N2Q + 255) / 256, 256>>>((const float4*)Wo, (uint2*)wh, (uint2*)wl, N2Q,
                                             nullptr, nullptr, nullptr, 0);
    proj_mma<<<pgrid, 256, PROJ_SMEM>>>(ch, cl, wh, wl, bo, out, nullptr, nullptr, 0);
}

// round 11
// speedup vs baseline: 1.0016x; 1.0016x over previous
#include <cuda_runtime.h>
#include <cuda_bf16.h>
#include <cstdint>
#include <math.h>

// Problem constants
#define B_  2
#define S_  2048
#define D_  1024
#define H_  16
#define DK_ 64
#define M_  (B_*S_)   // 4096

typedef __nv_bfloat16 bf16;

// Scratch (allocation-free rule: __device__ globals), all hi/lo bf16 planes
__device__ bf16 g_Ah[(size_t)M_*D_], g_Al[(size_t)M_*D_];   // split input (reused q/k/v)
__device__ bf16 g_Wh[(size_t)D_*D_], g_Wl[(size_t)D_*D_];   // split weight (reused)
__device__ bf16 g_Qh[(size_t)M_*D_], g_Ql[(size_t)M_*D_];   // [B,H,S,DK]
__device__ bf16 g_Kh[(size_t)M_*D_], g_Kl[(size_t)M_*D_];
__device__ bf16 g_Vh[(size_t)M_*D_], g_Vl[(size_t)M_*D_];
__device__ bf16 g_Ch[(size_t)M_*D_], g_Cl[(size_t)M_*D_];   // context [B,S,D]

// ---------------------------------------------------------------------------
// Helpers
// ---------------------------------------------------------------------------
__device__ __forceinline__ void ldm_x4(uint32_t* r, uint32_t addr) {
    asm volatile("ldmatrix.sync.aligned.m8n8.x4.shared.b16 {%0,%1,%2,%3}, [%4];"
        : "=r"(r[0]), "=r"(r[1]), "=r"(r[2]), "=r"(r[3]) : "r"(addr));
}
__device__ __forceinline__ void ldm_x4_t(uint32_t* r, uint32_t addr) {
    asm volatile("ldmatrix.sync.aligned.m8n8.x4.trans.shared.b16 {%0,%1,%2,%3}, [%4];"
        : "=r"(r[0]), "=r"(r[1]), "=r"(r[2]), "=r"(r[3]) : "r"(addr));
}
__device__ __forceinline__ void mma_bf16(float* c, const uint32_t* a, const uint32_t* b) {
    asm volatile("mma.sync.aligned.m16n8k16.row.col.f32.bf16.bf16.f32 "
        "{%0,%1,%2,%3}, {%4,%5,%6,%7}, {%8,%9}, {%0,%1,%2,%3};"
        : "+f"(c[0]), "+f"(c[1]), "+f"(c[2]), "+f"(c[3])
        : "r"(a[0]), "r"(a[1]), "r"(a[2]), "r"(a[3]), "r"(b[0]), "r"(b[1]));
}
__device__ __forceinline__ uint32_t pack_hi2(float x, float y) {
    __nv_bfloat162 t(__float2bfloat16_rn(x), __float2bfloat16_rn(y));
    return *(uint32_t*)&t;
}
__device__ __forceinline__ uint32_t pack_lo2(float x, float y) {
    bf16 hx = __float2bfloat16_rn(x);
    bf16 hy = __float2bfloat16_rn(y);
    __nv_bfloat162 t(__float2bfloat16_rn(x - __bfloat162float(hx)),
                     __float2bfloat16_rn(y - __bfloat162float(hy)));
    return *(uint32_t*)&t;
}
__device__ __forceinline__ void cp16(uint32_t saddr, const void* g) {
    asm volatile("cp.async.cg.shared.global [%0], [%1], 16;" :: "r"(saddr), "l"(g));
}

// ---------------------------------------------------------------------------
// Split fp32 -> hi/lo bf16 planes (two arrays per launch)
// ---------------------------------------------------------------------------
__global__ void split_kernel(const float4* __restrict__ in1, uint2* __restrict__ h1,
                             uint2* __restrict__ l1, int n1q,
                             const float4* __restrict__ in2, uint2* __restrict__ h2,
                             uint2* __restrict__ l2, int n2q)
{
    int i = blockIdx.x * blockDim.x + threadIdx.x;
    const float4* in; uint2 *oh, *ol; int idx;
    if (i < n1q) { in = in1; oh = h1; ol = l1; idx = i; }
    else { idx = i - n1q; if (idx >= n2q) return; in = in2; oh = h2; ol = l2; }
    float4 v = in[idx];
    uint2 ph, pl;
    ph.x = pack_hi2(v.x, v.y); ph.y = pack_hi2(v.z, v.w);
    pl.x = pack_lo2(v.x, v.y); pl.y = pack_lo2(v.z, v.w);
    oh[idx] = ph; ol[idx] = pl;
}

// ---------------------------------------------------------------------------
// Pure-bf16 projection GEMM, cp.async double-buffered.
// out = A @ W^T + bias  (A = Ah+Al, W = Wh+Wl, 3-MMA emulated fp32)
// CTA 128x128, BK=32, 8 warps (2x4, warp tile 64x32), 2 CTAs/SM.
// ---------------------------------------------------------------------------
#define LDK 40
#define PLB  (128 * LDK * 2)        // plane bytes
#define STGB (4 * PLB)              // stage bytes (Ah,Al,Wh,Wl)
#define PROJ_SMEM (2 * STGB)        // 81,920 B

__global__ __launch_bounds__(256, 2) void proj_mma(
    const bf16* __restrict__ Ah, const bf16* __restrict__ Al,
    const bf16* __restrict__ Wh, const bf16* __restrict__ Wl,
    const float* __restrict__ bias,
    float* __restrict__ outF, bf16* __restrict__ outH, bf16* __restrict__ outL,
    int headSplit)
{
    extern __shared__ char smem_raw[];
    uint32_t smem_b = (uint32_t)__cvta_generic_to_shared(smem_raw);

    const int tid  = threadIdx.x;
    const int lane = tid & 31;
    const int wrp  = tid >> 5;
    const int wr = wrp >> 2;
    const int wc = wrp & 3;
    const int bm = blockIdx.y * 128;
    const int bn = blockIdx.x * 128;

    const int lrow = tid >> 1;
    const int lseg = (tid & 1) * 16;
    const bf16* gAh = Ah + (size_t)(bm + lrow) * D_ + lseg;
    const bf16* gAl = Al + (size_t)(bm + lrow) * D_ + lseg;
    const bf16* gWh = Wh + (size_t)(bn + lrow) * D_ + lseg;
    const bf16* gWl = Wl + (size_t)(bn + lrow) * D_ + lseg;
    const uint32_t sdst = smem_b + (uint32_t)(lrow * LDK + lseg) * 2u;

    float acc[4][4][4];
    #pragma unroll
    for (int mt = 0; mt < 4; mt++)
        #pragma unroll
        for (int nt = 0; nt < 4; nt++)
            #pragma unroll
            for (int r = 0; r < 4; r++) acc[mt][nt][r] = 0.f;

    const int a_r = lane & 15;
    const int a_k = (lane >> 4) * 8;
    const int b_r = (lane & 7) + ((lane >> 4) << 3);
    const int b_k = ((lane >> 3) & 1) * 8;

    // issue loads for a stage
    auto issue = [&](int stage, int k0) {
        uint32_t sb = sdst + stage * STGB;
        cp16(sb,               gAh + k0);
        cp16(sb + 16,          gAh + k0 + 8);
        cp16(sb + PLB,         gAl + k0);
        cp16(sb + PLB + 16,    gAl + k0 + 8);
        cp16(sb + 2*PLB,       gWh + k0);
        cp16(sb + 2*PLB + 16,  gWh + k0 + 8);
        cp16(sb + 3*PLB,       gWl + k0);
        cp16(sb + 3*PLB + 16,  gWl + k0 + 8);
        asm volatile("cp.async.commit_group;");
    };

    issue(0, 0);

    for (int c = 0; c < D_ / 32; c++) {
        if (c < D_ / 32 - 1) issue((c + 1) & 1, (c + 1) * 32);
        if (c < D_ / 32 - 1) asm volatile("cp.async.wait_group 1;");
        else                 asm volatile("cp.async.wait_group 0;");
        __syncthreads();

        uint32_t sAh_b = smem_b + (c & 1) * STGB;
        uint32_t sAl_b = sAh_b + PLB;
        uint32_t sWh_b = sAh_b + 2 * PLB;
        uint32_t sWl_b = sAh_b + 3 * PLB;

        #pragma unroll
        for (int ks = 0; ks < 2; ks++) {
            const int k0 = ks * 16;
            uint32_t afh[4][4], afl[4][4];
            #pragma unroll
            for (int mt = 0; mt < 4; mt++) {
                int m0 = wr * 64 + mt * 16;
                uint32_t off = (uint32_t)((m0 + a_r) * LDK + k0 + a_k) * 2u;
                ldm_x4(afh[mt], sAh_b + off);
                ldm_x4(afl[mt], sAl_b + off);
            }
            uint32_t bfh[4][2], bfl[4][2];
            #pragma unroll
            for (int np = 0; np < 2; np++) {
                int n0 = wc * 32 + np * 16;
                uint32_t off = (uint32_t)((n0 + b_r) * LDK + k0 + b_k) * 2u;
                uint32_t th[4], tl[4];
                ldm_x4(th, sWh_b + off);
                ldm_x4(tl, sWl_b + off);
                bfh[2*np][0]   = th[0]; bfh[2*np][1]   = th[1];
                bfh[2*np+1][0] = th[2]; bfh[2*np+1][1] = th[3];
                bfl[2*np][0]   = tl[0]; bfl[2*np][1]   = tl[1];
                bfl[2*np+1][0] = tl[2]; bfl[2*np+1][1] = tl[3];
            }
            #pragma unroll
            for (int mt = 0; mt < 4; mt++)
                #pragma unroll
                for (int nt = 0; nt < 4; nt++) {
                    mma_bf16(acc[mt][nt], afh[mt], bfh[nt]);
                    mma_bf16(acc[mt][nt], afl[mt], bfh[nt]);
                    mma_bf16(acc[mt][nt], afh[mt], bfl[nt]);
                }
        }
        __syncthreads();
    }

    // Epilogue
    const int g  = lane >> 2;
    const int i4 = lane & 3;
    #pragma unroll
    for (int mt = 0; mt < 4; mt++) {
        #pragma unroll
        for (int nt = 0; nt < 4; nt++) {
            int m = bm + wr * 64 + mt * 16 + g;
            int n = bn + wc * 32 + nt * 8 + i4 * 2;
            float b0 = bias[n], b1 = bias[n + 1];
            #pragma unroll
            for (int hf = 0; hf < 2; hf++) {
                int mm = m + hf * 8;
                float v0 = acc[mt][nt][hf * 2 + 0] + b0;
                float v1 = acc[mt][nt][hf * 2 + 1] + b1;
                if (headSplit) {
                    int bb = mm >> 11;
                    int s  = mm & (S_ - 1);
                    int h  = n >> 6;
                    int dk = n & (DK_ - 1);
                    size_t off = ((size_t)((bb * H_ + h) * S_ + s)) * DK_ + dk;
                    *(uint32_t*)(outH + off) = pack_hi2(v0, v1);
                    *(uint32_t*)(outL + off) = pack_lo2(v0, v1);
                } else {
                    *(float2*)(outF + (size_t)mm * D_ + n) = make_float2(v0, v1);
                }
            }
        }
    }
}

// ---------------------------------------------------------------------------
// Flash-attention on tensor cores, all operands pre-split bf16.
// CTA: 128 q-rows per (b,h). 8 warps x 16 rows, warp-local softmax,
// P in registers (C-frag == A-frag). 82.9 KB SMEM, 2 CTAs/SM.
// ---------------------------------------------------------------------------
#define LQ 72
#define ATTN_SMEM ((128*LQ + 64*LQ + 64*LQ) * 2 * 2 + 128*LQ)   // 82,944 B

__global__ __launch_bounds__(256, 2) void attn_mma(const int* __restrict__ mask)
{
    extern __shared__ char smem_raw[];
    bf16* Qh = (bf16*)smem_raw;
    bf16* Ql = Qh + 128 * LQ;
    bf16* Kh = Ql + 128 * LQ;
    bf16* Kl = Kh + 64 * LQ;
    bf16* Vh = Kl + 64 * LQ;
    bf16* Vl = Vh + 64 * LQ;
    uint8_t* Ms = (uint8_t*)(Vl + 64 * LQ);

    const int tid  = threadIdx.x;
    const int lane = tid & 31;
    const int warp = tid >> 5;
    const int b = blockIdx.z, h = blockIdx.y;
    const int q0 = blockIdx.x * 128;

    const size_t bh = ((size_t)(b * H_ + h)) * S_ * DK_;
    const bf16* Qhg = g_Qh + bh; const bf16* Qlg = g_Ql + bh;
    const bf16* Khg = g_Kh + bh; const bf16* Klg = g_Kl + bh;
    const bf16* Vhg = g_Vh + bh; const bf16* Vlg = g_Vl + bh;
    const int*  mb  = mask + (size_t)b * S_ * S_;

    uint32_t Qh_b = (uint32_t)__cvta_generic_to_shared(Qh);
    uint32_t Ql_b = (uint32_t)__cvta_generic_to_shared(Ql);
    uint32_t Kh_b = (uint32_t)__cvta_generic_to_shared(Kh);
    uint32_t Kl_b = (uint32_t)__cvta_generic_to_shared(Kl);
    uint32_t Vh_b = (uint32_t)__cvta_generic_to_shared(Vh);
    uint32_t Vl_b = (uint32_t)__cvta_generic_to_shared(Vl);

    // Load Q tile (row = tid>>1, 32-col half) — straight bf16 copies
    {
        int row = tid >> 1, seg = (tid & 1) * 32;
        const uint4* sh = (const uint4*)(Qhg + (size_t)(q0 + row) * DK_ + seg);
        const uint4* sl = (const uint4*)(Qlg + (size_t)(q0 + row) * DK_ + seg);
        uint4* dh = (uint4*)(Qh + row * LQ + seg);
        uint4* dl = (uint4*)(Ql + row * LQ + seg);
        #pragma unroll
        for (int u = 0; u < 4; u++) { dh[u] = sh[u]; dl[u] = sl[u]; }
    }

    float m_i[2] = { -INFINITY, -INFINITY };
    float l_i[2] = { 0.f, 0.f };
    float o[8][4];
    #pragma unroll
    for (int nt = 0; nt < 8; nt++)
        #pragma unroll
        for (int r = 0; r < 4; r++) o[nt][r] = 0.f;

    const int a_r = lane & 15;
    const int a_k = (lane >> 4) * 8;
    const int b_r = (lane & 7) + ((lane >> 4) << 3);
    const int b_k = ((lane >> 3) & 1) * 8;
    const int t_r = (lane & 7) + (((lane >> 3) & 1) << 3);
    const int t_c = (lane >> 4) * 8;

    for (int k0 = 0; k0 < S_; k0 += 64) {
        __syncthreads();

        // K/V tile copy (row = tid>>2, 16-col quarter)
        {
            int row = tid >> 2, seg = (tid & 3) * 16;
            size_t go = (size_t)(k0 + row) * DK_ + seg;
            int so = row * LQ + seg;
            #pragma unroll
            for (int u = 0; u < 2; u++) {
                ((uint4*)(Kh + so))[u] = ((const uint4*)(Khg + go))[u];
                ((uint4*)(Kl + so))[u] = ((const uint4*)(Klg + go))[u];
                ((uint4*)(Vh + so))[u] = ((const uint4*)(Vhg + go))[u];
                ((uint4*)(Vl + so))[u] = ((const uint4*)(Vlg + go))[u];
            }
        }
        // mask tile -> bytes
        {
            int row = tid >> 1, seg = (tid & 1) * 32;
            const int* mrow = mb + (size_t)(q0 + row) * S_ + k0 + seg;
            #pragma unroll
            for (int u = 0; u < 8; u++) {
                int4 m4 = *(const int4*)(mrow + u * 4);
                uchar4 cc;
                cc.x = (unsigned char)m4.x; cc.y = (unsigned char)m4.y;
                cc.z = (unsigned char)m4.z; cc.w = (unsigned char)m4.w;
                *(uchar4*)(Ms + row * LQ + seg + u * 4) = cc;
            }
        }
        __syncthreads();

        // ---- S = Q @ K^T ----
        float s[8][4];
        #pragma unroll
        for (int nt = 0; nt < 8; nt++)
            #pragma unroll
            for (int r = 0; r < 4; r++) s[nt][r] = 0.f;

        #pragma unroll
        for (int kt = 0; kt < 4; kt++) {
            uint32_t ah[4], al[4];
            uint32_t aoff = (uint32_t)((warp * 16 + a_r) * LQ + kt * 16 + a_k) * 2u;
            ldm_x4(ah, Qh_b + aoff);
            ldm_x4(al, Ql_b + aoff);
            #pragma unroll
            for (int nc = 0; nc < 4; nc++) {
                uint32_t bhf[4], blf[4];
                uint32_t boff = (uint32_t)((nc * 16 + b_r) * LQ + kt * 16 + b_k) * 2u;
                ldm_x4(bhf, Kh_b + boff);
                ldm_x4(blf, Kl_b + boff);
                mma_bf16(s[2*nc],   ah, &bhf[0]);
                mma_bf16(s[2*nc],   al, &bhf[0]);
                mma_bf16(s[2*nc],   ah, &blf[0]);
                mma_bf16(s[2*nc+1], ah, &bhf[2]);
                mma_bf16(s[2*nc+1], al, &bhf[2]);
                mma_bf16(s[2*nc+1], ah, &blf[2]);
            }
        }

        // ---- mask + online softmax ----
        const int grow0 = warp * 16 + (lane >> 2);
        const int cb = (lane & 3) * 2;
        #pragma unroll
        for (int r = 0; r < 2; r++) {
            int grow = grow0 + r * 8;
            float tmax = -INFINITY;
            #pragma unroll
            for (int nt = 0; nt < 8; nt++) {
                uint8_t mk0 = Ms[grow * LQ + nt * 8 + cb];
                uint8_t mk1 = Ms[grow * LQ + nt * 8 + cb + 1];
                float v0 = mk0 ? s[nt][r*2+0] * 0.125f : -1e9f;
                float v1 = mk1 ? s[nt][r*2+1] * 0.125f : -1e9f;
                s[nt][r*2+0] = v0; s[nt][r*2+1] = v1;
                tmax = fmaxf(tmax, fmaxf(v0, v1));
            }
            tmax = fmaxf(tmax, __shfl_xor_sync(0xffffffffu, tmax, 1));
            tmax = fmaxf(tmax, __shfl_xor_sync(0xffffffffu, tmax, 2));
            float mnew = fmaxf(m_i[r], tmax);
            float esc = __expf(m_i[r] - mnew);
            float rs = 0.f;
            #pragma unroll
            for (int nt = 0; nt < 8; nt++) {
                float p0 = __expf(s[nt][r*2+0] - mnew);
                float p1 = __expf(s[nt][r*2+1] - mnew);
                s[nt][r*2+0] = p0; s[nt][r*2+1] = p1;
                rs += p0 + p1;
            }
            rs += __shfl_xor_sync(0xffffffffu, rs, 1);
            rs += __shfl_xor_sync(0xffffffffu, rs, 2);
            l_i[r] = l_i[r] * esc + rs;
            m_i[r] = mnew;
            #pragma unroll
            for (int nt = 0; nt < 8; nt++) {
                o[nt][r*2+0] *= esc;
                o[nt][r*2+1] *= esc;
            }
        }

        // P C-frag -> A-frag packs (hi/lo)
        uint32_t pfh[4][4], pfl[4][4];
        #pragma unroll
        for (int kt = 0; kt < 4; kt++) {
            pfh[kt][0] = pack_hi2(s[2*kt][0],   s[2*kt][1]);
            pfh[kt][1] = pack_hi2(s[2*kt][2],   s[2*kt][3]);
            pfh[kt][2] = pack_hi2(s[2*kt+1][0], s[2*kt+1][1]);
            pfh[kt][3] = pack_hi2(s[2*kt+1][2], s[2*kt+1][3]);
            pfl[kt][0] = pack_lo2(s[2*kt][0],   s[2*kt][1]);
            pfl[kt][1] = pack_lo2(s[2*kt][2],   s[2*kt][3]);
            pfl[kt][2] = pack_lo2(s[2*kt+1][0], s[2*kt+1][1]);
            pfl[kt][3] = pack_lo2(s[2*kt+1][2], s[2*kt+1][3]);
        }

        // ---- O += P @ V ----
        #pragma unroll
        for (int kt = 0; kt < 4; kt++) {
            #pragma unroll
            for (int nd = 0; nd < 4; nd++) {
                uint32_t vh_[4], vl_[4];
                uint32_t voff = (uint32_t)((kt * 16 + t_r) * LQ + nd * 16 + t_c) * 2u;
                ldm_x4_t(vh_, Vh_b + voff);
                ldm_x4_t(vl_, Vl_b + voff);
                mma_bf16(o[2*nd],   pfh[kt], &vh_[0]);
                mma_bf16(o[2*nd],   pfl[kt], &vh_[0]);
                mma_bf16(o[2*nd],   pfh[kt], &vl_[0]);
                mma_bf16(o[2*nd+1], pfh[kt], &vh_[2]);
                mma_bf16(o[2*nd+1], pfl[kt], &vh_[2]);
                mma_bf16(o[2*nd+1], pfh[kt], &vl_[2]);
            }
        }
    }

    // Epilogue: normalize, write context hi/lo bf16 planes [B,S,D]
    #pragma unroll
    for (int r = 0; r < 2; r++) {
        int q = q0 + warp * 16 + (lane >> 2) + r * 8;
        float inv = 1.f / l_i[r];
        #pragma unroll
        for (int nt = 0; nt < 8; nt++) {
            float v0 = o[nt][r*2+0] * inv;
            float v1 = o[nt][r*2+1] * inv;
            size_t off = ((size_t)(b * S_ + q)) * D_ + h * DK_ + nt * 8 + (lane & 3) * 2;
            *(uint32_t*)(g_Ch + off) = pack_hi2(v0, v1);
            *(uint32_t*)(g_Cl + off) = pack_lo2(v0, v1);
        }
    }
}

// ---------------------------------------------------------------------------
// Launch
// ---------------------------------------------------------------------------
extern "C" void kernel_launch(void* const* d_in, const int* in_sizes, int n_in,
                              void* d_out, int out_size)
{
    const float* input_q = (const float*)d_in[0];
    const float* input_k = (const float*)d_in[1];
    const float* input_v = (const float*)d_in[2];
    const int*   mask    = (const int*)  d_in[3];
    const float* Wq = (const float*)d_in[4];
    const float* bq = (const float*)d_in[5];
    const float* Wk = (const float*)d_in[6];
    const float* bk = (const float*)d_in[7];
    const float* Wv = (const float*)d_in[8];
    const float* bv = (const float*)d_in[9];
    const float* Wo = (const float*)d_in[10];
    const float* bo = (const float*)d_in[11];
    float* out = (float*)d_out;

    bf16 *ah, *al, *wh, *wl, *qh, *ql, *kh, *kl, *vh, *vl, *ch, *cl;
    cudaGetSymbolAddress((void**)&ah, g_Ah); cudaGetSymbolAddress((void**)&al, g_Al);
    cudaGetSymbolAddress((void**)&wh, g_Wh); cudaGetSymbolAddress((void**)&wl, g_Wl);
    cudaGetSymbolAddress((void**)&qh, g_Qh); cudaGetSymbolAddress((void**)&ql, g_Ql);
    cudaGetSymbolAddress((void**)&kh, g_Kh); cudaGetSymbolAddress((void**)&kl, g_Kl);
    cudaGetSymbolAddress((void**)&vh, g_Vh); cudaGetSymbolAddress((void**)&vl, g_Vl);
    cudaGetSymbolAddress((void**)&ch, g_Ch); cudaGetSymbolAddress((void**)&cl, g_Cl);

    cudaFuncSetAttribute(proj_mma,
                         cudaFuncAttributeMaxDynamicSharedMemorySize, PROJ_SMEM);
    cudaFuncSetAttribute(attn_mma,
                         cudaFuncAttributeMaxDynamicSharedMemorySize, ATTN_SMEM);

    const int N1Q = M_ * D_ / 4;   // input quads
    const int N2Q = D_ * D_ / 4;   // weight quads
    const int SPLIT_BLK = (N1Q + N2Q + 255) / 256;
    dim3 pgrid(D_ / 128, M_ / 128);   // (8, 32)
    dim3 agrid(S_ / 128, H_, B_);     // (16, 16, 2)

    // Q
    split_kernel<<<SPLIT_BLK, 256>>>((const float4*)input_q, (uint2*)ah, (uint2*)al, N1Q,
                                     (const float4*)Wq, (uint2*)wh, (uint2*)wl, N2Q);
    proj_mma<<<pgrid, 256, PROJ_SMEM>>>(ah, al, wh, wl, bq, nullptr, qh, ql, 1);
    // K
    split_kernel<<<SPLIT_BLK, 256>>>((const float4*)input_k, (uint2*)ah, (uint2*)al, N1Q,
                                     (const float4*)Wk, (uint2*)wh, (uint2*)wl, N2Q);
    proj_mma<<<pgrid, 256, PROJ_SMEM>>>(ah, al, wh, wl, bk, nullptr, kh, kl, 1);
    // V
    split_kernel<<<SPLIT_BLK, 256>>>((const float4*)input_v, (uint2*)ah, (uint2*)al, N1Q,
                                     (const float4*)Wv, (uint2*)wh, (uint2*)wl, N2Q);
    proj_mma<<<pgrid, 256, PROJ_SMEM>>>(ah, al, wh, wl, bv, nullptr, vh, vl, 1);
    // attention
    attn_mma<<<agrid, 256, ATTN_SMEM>>>(mask);
    // output projection
    split_kernel<<<(N2Q + 255) / 256, 256>>>((const float4*)Wo, (uint2*)wh, (uint2*)wl, N2Q,
                                             nullptr, nullptr, nullptr, 0);
    proj_mma<<<pgrid, 256, PROJ_SMEM>>>(ch, cl, wh, wl, bo, out, nullptr, nullptr, 0);
}

// round 12
// speedup vs baseline: 1.0019x; 1.0003x over previous
#include <cuda_runtime.h>
#include <cuda_bf16.h>
#include <cstdint>
#include <math.h>

// Problem constants
#define B_  2
#define S_  2048
#define D_  1024
#define H_  16
#define DK_ 64
#define M_  (B_*S_)   // 4096

typedef __nv_bfloat16 bf16;

// Scratch (allocation-free rule: __device__ globals), all hi/lo bf16 planes
__device__ bf16 g_Ah[(size_t)M_*D_], g_Al[(size_t)M_*D_];   // split input (reused q/k/v)
__device__ bf16 g_Wh[(size_t)D_*D_], g_Wl[(size_t)D_*D_];   // split weight (reused)
__device__ bf16 g_Qh[(size_t)M_*D_], g_Ql[(size_t)M_*D_];   // [B,H,S,DK]
__device__ bf16 g_Kh[(size_t)M_*D_], g_Kl[(size_t)M_*D_];
__device__ bf16 g_Vh[(size_t)M_*D_], g_Vl[(size_t)M_*D_];
__device__ bf16 g_Ch[(size_t)M_*D_], g_Cl[(size_t)M_*D_];   // context [B,S,D]

// ---------------------------------------------------------------------------
// Helpers
// ---------------------------------------------------------------------------
__device__ __forceinline__ void ldm_x4(uint32_t* r, uint32_t addr) {
    asm volatile("ldmatrix.sync.aligned.m8n8.x4.shared.b16 {%0,%1,%2,%3}, [%4];"
        : "=r"(r[0]), "=r"(r[1]), "=r"(r[2]), "=r"(r[3]) : "r"(addr));
}
__device__ __forceinline__ void ldm_x4_t(uint32_t* r, uint32_t addr) {
    asm volatile("ldmatrix.sync.aligned.m8n8.x4.trans.shared.b16 {%0,%1,%2,%3}, [%4];"
        : "=r"(r[0]), "=r"(r[1]), "=r"(r[2]), "=r"(r[3]) : "r"(addr));
}
__device__ __forceinline__ void mma_bf16(float* c, const uint32_t* a, const uint32_t* b) {
    asm volatile("mma.sync.aligned.m16n8k16.row.col.f32.bf16.bf16.f32 "
        "{%0,%1,%2,%3}, {%4,%5,%6,%7}, {%8,%9}, {%0,%1,%2,%3};"
        : "+f"(c[0]), "+f"(c[1]), "+f"(c[2]), "+f"(c[3])
        : "r"(a[0]), "r"(a[1]), "r"(a[2]), "r"(a[3]), "r"(b[0]), "r"(b[1]));
}
__device__ __forceinline__ uint32_t pack_hi2(float x, float y) {
    __nv_bfloat162 t(__float2bfloat16_rn(x), __float2bfloat16_rn(y));
    return *(uint32_t*)&t;
}
__device__ __forceinline__ uint32_t pack_lo2(float x, float y) {
    bf16 hx = __float2bfloat16_rn(x);
    bf16 hy = __float2bfloat16_rn(y);
    __nv_bfloat162 t(__float2bfloat16_rn(x - __bfloat162float(hx)),
                     __float2bfloat16_rn(y - __bfloat162float(hy)));
    return *(uint32_t*)&t;
}
__device__ __forceinline__ void cp16(uint32_t saddr, const void* g) {
    asm volatile("cp.async.cg.shared.global [%0], [%1], 16;" :: "r"(saddr), "l"(g));
}

// ---------------------------------------------------------------------------
// Split fp32 -> hi/lo bf16 planes (two arrays per launch)
// ---------------------------------------------------------------------------
__global__ void split_kernel(const float4* __restrict__ in1, uint2* __restrict__ h1,
                             uint2* __restrict__ l1, int n1q,
                             const float4* __restrict__ in2, uint2* __restrict__ h2,
                             uint2* __restrict__ l2, int n2q)
{
    int i = blockIdx.x * blockDim.x + threadIdx.x;
    const float4* in; uint2 *oh, *ol; int idx;
    if (i < n1q) { in = in1; oh = h1; ol = l1; idx = i; }
    else { idx = i - n1q; if (idx >= n2q) return; in = in2; oh = h2; ol = l2; }
    float4 v = in[idx];
    uint2 ph, pl;
    ph.x = pack_hi2(v.x, v.y); ph.y = pack_hi2(v.z, v.w);
    pl.x = pack_lo2(v.x, v.y); pl.y = pack_lo2(v.z, v.w);
    oh[idx] = ph; ol[idx] = pl;
}

// ---------------------------------------------------------------------------
// Pure-bf16 projection GEMM, cp.async double-buffered.
// out = A @ W^T + bias  (A = Ah+Al, W = Wh+Wl, 3-MMA emulated fp32)
// CTA 128x128, BK=32, 8 warps (2x4, warp tile 64x32), 2 CTAs/SM.
// ---------------------------------------------------------------------------
#define LDK 40
#define PLB  (128 * LDK * 2)        // plane bytes
#define STGB (4 * PLB)              // stage bytes (Ah,Al,Wh,Wl)
#define PROJ_SMEM (2 * STGB)        // 81,920 B

__global__ __launch_bounds__(256, 2) void proj_mma(
    const bf16* __restrict__ Ah, const bf16* __restrict__ Al,
    const bf16* __restrict__ Wh, const bf16* __restrict__ Wl,
    const float* __restrict__ bias,
    float* __restrict__ outF, bf16* __restrict__ outH, bf16* __restrict__ outL,
    int headSplit)
{
    extern __shared__ char smem_raw[];
    uint32_t smem_b = (uint32_t)__cvta_generic_to_shared(smem_raw);

    const int tid  = threadIdx.x;
    const int lane = tid & 31;
    const int wrp  = tid >> 5;
    const int wr = wrp >> 2;
    const int wc = wrp & 3;
    const int bm = blockIdx.y * 128;
    const int bn = blockIdx.x * 128;

    const int lrow = tid >> 1;
    const int lseg = (tid & 1) * 16;
    const bf16* gAh = Ah + (size_t)(bm + lrow) * D_ + lseg;
    const bf16* gAl = Al + (size_t)(bm + lrow) * D_ + lseg;
    const bf16* gWh = Wh + (size_t)(bn + lrow) * D_ + lseg;
    const bf16* gWl = Wl + (size_t)(bn + lrow) * D_ + lseg;
    const uint32_t sdst = smem_b + (uint32_t)(lrow * LDK + lseg) * 2u;

    float acc[4][4][4];
    #pragma unroll
    for (int mt = 0; mt < 4; mt++)
        #pragma unroll
        for (int nt = 0; nt < 4; nt++)
            #pragma unroll
            for (int r = 0; r < 4; r++) acc[mt][nt][r] = 0.f;

    const int a_r = lane & 15;
    const int a_k = (lane >> 4) * 8;
    const int b_r = (lane & 7) + ((lane >> 4) << 3);
    const int b_k = ((lane >> 3) & 1) * 8;

    // issue loads for a stage
    auto issue = [&](int stage, int k0) {
        uint32_t sb = sdst + stage * STGB;
        cp16(sb,               gAh + k0);
        cp16(sb + 16,          gAh + k0 + 8);
        cp16(sb + PLB,         gAl + k0);
        cp16(sb + PLB + 16,    gAl + k0 + 8);
        cp16(sb + 2*PLB,       gWh + k0);
        cp16(sb + 2*PLB + 16,  gWh + k0 + 8);
        cp16(sb + 3*PLB,       gWl + k0);
        cp16(sb + 3*PLB + 16,  gWl + k0 + 8);
        asm volatile("cp.async.commit_group;");
    };

    issue(0, 0);

    for (int c = 0; c < D_ / 32; c++) {
        if (c < D_ / 32 - 1) issue((c + 1) & 1, (c + 1) * 32);
        if (c < D_ / 32 - 1) asm volatile("cp.async.wait_group 1;");
        else                 asm volatile("cp.async.wait_group 0;");
        __syncthreads();

        uint32_t sAh_b = smem_b + (c & 1) * STGB;
        uint32_t sAl_b = sAh_b + PLB;
        uint32_t sWh_b = sAh_b + 2 * PLB;
        uint32_t sWl_b = sAh_b + 3 * PLB;

        #pragma unroll
        for (int ks = 0; ks < 2; ks++) {
            const int k0 = ks * 16;
            uint32_t afh[4][4], afl[4][4];
            #pragma unroll
            for (int mt = 0; mt < 4; mt++) {
                int m0 = wr * 64 + mt * 16;
                uint32_t off = (uint32_t)((m0 + a_r) * LDK + k0 + a_k) * 2u;
                ldm_x4(afh[mt], sAh_b + off);
                ldm_x4(afl[mt], sAl_b + off);
            }
            uint32_t bfh[4][2], bfl[4][2];
            #pragma unroll
            for (int np = 0; np < 2; np++) {
                int n0 = wc * 32 + np * 16;
                uint32_t off = (uint32_t)((n0 + b_r) * LDK + k0 + b_k) * 2u;
                uint32_t th[4], tl[4];
                ldm_x4(th, sWh_b + off);
                ldm_x4(tl, sWl_b + off);
                bfh[2*np][0]   = th[0]; bfh[2*np][1]   = th[1];
                bfh[2*np+1][0] = th[2]; bfh[2*np+1][1] = th[3];
                bfl[2*np][0]   = tl[0]; bfl[2*np][1]   = tl[1];
                bfl[2*np+1][0] = tl[2]; bfl[2*np+1][1] = tl[3];
            }
            #pragma unroll
            for (int mt = 0; mt < 4; mt++)
                #pragma unroll
                for (int nt = 0; nt < 4; nt++) {
                    mma_bf16(acc[mt][nt], afh[mt], bfh[nt]);
                    mma_bf16(acc[mt][nt], afl[mt], bfh[nt]);
                    mma_bf16(acc[mt][nt], afh[mt], bfl[nt]);
                }
        }
        __syncthreads();
    }

    // Epilogue
    const int g  = lane >> 2;
    const int i4 = lane & 3;
    #pragma unroll
    for (int mt = 0; mt < 4; mt++) {
        #pragma unroll
        for (int nt = 0; nt < 4; nt++) {
            int m = bm + wr * 64 + mt * 16 + g;
            int n = bn + wc * 32 + nt * 8 + i4 * 2;
            float b0 = bias[n], b1 = bias[n + 1];
            #pragma unroll
            for (int hf = 0; hf < 2; hf++) {
                int mm = m + hf * 8;
                float v0 = acc[mt][nt][hf * 2 + 0] + b0;
                float v1 = acc[mt][nt][hf * 2 + 1] + b1;
                if (headSplit) {
                    int bb = mm >> 11;
                    int s  = mm & (S_ - 1);
                    int h  = n >> 6;
                    int dk = n & (DK_ - 1);
                    size_t off = ((size_t)((bb * H_ + h) * S_ + s)) * DK_ + dk;
                    *(uint32_t*)(outH + off) = pack_hi2(v0, v1);
                    *(uint32_t*)(outL + off) = pack_lo2(v0, v1);
                } else {
                    *(float2*)(outF + (size_t)mm * D_ + n) = make_float2(v0, v1);
                }
            }
        }
    }
}

// ---------------------------------------------------------------------------
// Flash-attention on tensor cores, all operands pre-split bf16.
// CTA: 128 q-rows per (b,h). 8 warps x 16 rows, warp-local softmax,
// P in registers (C-frag == A-frag). 82.9 KB SMEM, 2 CTAs/SM.
// ---------------------------------------------------------------------------
#define LQ 72
#define ATTN_SMEM ((128*LQ + 64*LQ + 64*LQ) * 2 * 2 + 128*LQ)   // 82,944 B

__global__ __launch_bounds__(256, 2) void attn_mma(const int* __restrict__ mask)
{
    extern __shared__ char smem_raw[];
    bf16* Qh = (bf16*)smem_raw;
    bf16* Ql = Qh + 128 * LQ;
    bf16* Kh = Ql + 128 * LQ;
    bf16* Kl = Kh + 64 * LQ;
    bf16* Vh = Kl + 64 * LQ;
    bf16* Vl = Vh + 64 * LQ;
    uint8_t* Ms = (uint8_t*)(Vl + 64 * LQ);

    const int tid  = threadIdx.x;
    const int lane = tid & 31;
    const int warp = tid >> 5;
    const int b = blockIdx.z, h = blockIdx.y;
    const int q0 = blockIdx.x * 128;

    const size_t bh = ((size_t)(b * H_ + h)) * S_ * DK_;
    const bf16* Qhg = g_Qh + bh; const bf16* Qlg = g_Ql + bh;
    const bf16* Khg = g_Kh + bh; const bf16* Klg = g_Kl + bh;
    const bf16* Vhg = g_Vh + bh; const bf16* Vlg = g_Vl + bh;
    const int*  mb  = mask + (size_t)b * S_ * S_;

    uint32_t Qh_b = (uint32_t)__cvta_generic_to_shared(Qh);
    uint32_t Ql_b = (uint32_t)__cvta_generic_to_shared(Ql);
    uint32_t Kh_b = (uint32_t)__cvta_generic_to_shared(Kh);
    uint32_t Kl_b = (uint32_t)__cvta_generic_to_shared(Kl);
    uint32_t Vh_b = (uint32_t)__cvta_generic_to_shared(Vh);
    uint32_t Vl_b = (uint32_t)__cvta_generic_to_shared(Vl);

    // Load Q tile (row = tid>>1, 32-col half) — straight bf16 copies
    {
        int row = tid >> 1, seg = (tid & 1) * 32;
        const uint4* sh = (const uint4*)(Qhg + (size_t)(q0 + row) * DK_ + seg);
        const uint4* sl = (const uint4*)(Qlg + (size_t)(q0 + row) * DK_ + seg);
        uint4* dh = (uint4*)(Qh + row * LQ + seg);
        uint4* dl = (uint4*)(Ql + row * LQ + seg);
        #pragma unroll
        for (int u = 0; u < 4; u++) { dh[u] = sh[u]; dl[u] = sl[u]; }
    }

    float m_i[2] = { -INFINITY, -INFINITY };
    float l_i[2] = { 0.f, 0.f };
    float o[8][4];
    #pragma unroll
    for (int nt = 0; nt < 8; nt++)
        #pragma unroll
        for (int r = 0; r < 4; r++) o[nt][r] = 0.f;

    const int a_r = lane & 15;
    const int a_k = (lane >> 4) * 8;
    const int b_r = (lane & 7) + ((lane >> 4) << 3);
    const int b_k = ((lane >> 3) & 1) * 8;
    const int t_r = (lane & 7) + (((lane >> 3) & 1) << 3);
    const int t_c = (lane >> 4) * 8;

    for (int k0 = 0; k0 < S_; k0 += 64) {
        __syncthreads();

        // K/V tile copy (row = tid>>2, 16-col quarter)
        {
            int row = tid >> 2, seg = (tid & 3) * 16;
            size_t go = (size_t)(k0 + row) * DK_ + seg;
            int so = row * LQ + seg;
            #pragma unroll
            for (int u = 0; u < 2; u++) {
                ((uint4*)(Kh + so))[u] = ((const uint4*)(Khg + go))[u];
                ((uint4*)(Kl + so))[u] = ((const uint4*)(Klg + go))[u];
                ((uint4*)(Vh + so))[u] = ((const uint4*)(Vhg + go))[u];
                ((uint4*)(Vl + so))[u] = ((const uint4*)(Vlg + go))[u];
            }
        }
        // mask tile -> bytes
        {
            int row = tid >> 1, seg = (tid & 1) * 32;
            const int* mrow = mb + (size_t)(q0 + row) * S_ + k0 + seg;
            #pragma unroll
            for (int u = 0; u < 8; u++) {
                int4 m4 = *(const int4*)(mrow + u * 4);
                uchar4 cc;
                cc.x = (unsigned char)m4.x; cc.y = (unsigned char)m4.y;
                cc.z = (unsigned char)m4.z; cc.w = (unsigned char)m4.w;
                *(uchar4*)(Ms + row * LQ + seg + u * 4) = cc;
            }
        }
        __syncthreads();

        // ---- S = Q @ K^T ----
        float s[8][4];
        #pragma unroll
        for (int nt = 0; nt < 8; nt++)
            #pragma unroll
            for (int r = 0; r < 4; r++) s[nt][r] = 0.f;

        #pragma unroll
        for (int kt = 0; kt < 4; kt++) {
            uint32_t ah[4], al[4];
            uint32_t aoff = (uint32_t)((warp * 16 + a_r) * LQ + kt * 16 + a_k) * 2u;
            ldm_x4(ah, Qh_b + aoff);
            ldm_x4(al, Ql_b + aoff);
            #pragma unroll
            for (int nc = 0; nc < 4; nc++) {
                uint32_t bhf[4], blf[4];
                uint32_t boff = (uint32_t)((nc * 16 + b_r) * LQ + kt * 16 + b_k) * 2u;
                ldm_x4(bhf, Kh_b + boff);
                ldm_x4(blf, Kl_b + boff);
                mma_bf16(s[2*nc],   ah, &bhf[0]);
                mma_bf16(s[2*nc],   al, &bhf[0]);
                mma_bf16(s[2*nc],   ah, &blf[0]);
                mma_bf16(s[2*nc+1], ah, &bhf[2]);
                mma_bf16(s[2*nc+1], al, &bhf[2]);
                mma_bf16(s[2*nc+1], ah, &blf[2]);
            }
        }

        // ---- mask + online softmax ----
        const int grow0 = warp * 16 + (lane >> 2);
        const int cb = (lane & 3) * 2;
        #pragma unroll
        for (int r = 0; r < 2; r++) {
            int grow = grow0 + r * 8;
            float tmax = -INFINITY;
            #pragma unroll
            for (int nt = 0; nt < 8; nt++) {
                uint8_t mk0 = Ms[grow * LQ + nt * 8 + cb];
                uint8_t mk1 = Ms[grow * LQ + nt * 8 + cb + 1];
                float v0 = mk0 ? s[nt][r*2+0] * 0.125f : -1e9f;
                float v1 = mk1 ? s[nt][r*2+1] * 0.125f : -1e9f;
                s[nt][r*2+0] = v0; s[nt][r*2+1] = v1;
                tmax = fmaxf(tmax, fmaxf(v0, v1));
            }
            tmax = fmaxf(tmax, __shfl_xor_sync(0xffffffffu, tmax, 1));
            tmax = fmaxf(tmax, __shfl_xor_sync(0xffffffffu, tmax, 2));
            float mnew = fmaxf(m_i[r], tmax);
            float esc = __expf(m_i[r] - mnew);
            float rs = 0.f;
            #pragma unroll
            for (int nt = 0; nt < 8; nt++) {
                float p0 = __expf(s[nt][r*2+0] - mnew);
                float p1 = __expf(s[nt][r*2+1] - mnew);
                s[nt][r*2+0] = p0; s[nt][r*2+1] = p1;
                rs += p0 + p1;
            }
            rs += __shfl_xor_sync(0xffffffffu, rs, 1);
            rs += __shfl_xor_sync(0xffffffffu, rs, 2);
            l_i[r] = l_i[r] * esc + rs;
            m_i[r] = mnew;
            #pragma unroll
            for (int nt = 0; nt < 8; nt++) {
                o[nt][r*2+0] *= esc;
                o[nt][r*2+1] *= esc;
            }
        }

        // P C-frag -> A-frag packs (hi/lo)
        uint32_t pfh[4][4], pfl[4][4];
        #pragma unroll
        for (int kt = 0; kt < 4; kt++) {
            pfh[kt][0] = pack_hi2(s[2*kt][0],   s[2*kt][1]);
            pfh[kt][1] = pack_hi2(s[2*kt][2],   s[2*kt][3]);
            pfh[kt][2] = pack_hi2(s[2*kt+1][0], s[2*kt+1][1]);
            pfh[kt][3] = pack_hi2(s[2*kt+1][2], s[2*kt+1][3]);
            pfl[kt][0] = pack_lo2(s[2*kt][0],   s[2*kt][1]);
            pfl[kt][1] = pack_lo2(s[2*kt][2],   s[2*kt][3]);
            pfl[kt][2] = pack_lo2(s[2*kt+1][0], s[2*kt+1][1]);
            pfl[kt][3] = pack_lo2(s[2*kt+1][2], s[2*kt+1][3]);
        }

        // ---- O += P @ V ----
        #pragma unroll
        for (int kt = 0; kt < 4; kt++) {
            #pragma unroll
            for (int nd = 0; nd < 4; nd++) {
                uint32_t vh_[4], vl_[4];
                uint32_t voff = (uint32_t)((kt * 16 + t_r) * LQ + nd * 16 + t_c) * 2u;
                ldm_x4_t(vh_, Vh_b + voff);
                ldm_x4_t(vl_, Vl_b + voff);
                mma_bf16(o[2*nd],   pfh[kt], &vh_[0]);
                mma_bf16(o[2*nd],   pfl[kt], &vh_[0]);
                mma_bf16(o[2*nd],   pfh[kt], &vl_[0]);
                mma_bf16(o[2*nd+1], pfh[kt], &vh_[2]);
                mma_bf16(o[2*nd+1], pfl[kt], &vh_[2]);
                mma_bf16(o[2*nd+1], pfh[kt], &vl_[2]);
            }
        }
    }

    // Epilogue: normalize, write context hi/lo bf16 planes [B,S,D]
    #pragma unroll
    for (int r = 0; r < 2; r++) {
        int q = q0 + warp * 16 + (lane >> 2) + r * 8;
        float inv = 1.f / l_i[r];
        #pragma unroll
        for (int nt = 0; nt < 8; nt++) {
            float v0 = o[nt][r*2+0] * inv;
            float v1 = o[nt][r*2+1] * inv;
            size_t off = ((size_t)(b * S_ + q)) * D_ + h * DK_ + nt * 8 + (lane & 3) * 2;
            *(uint32_t*)(g_Ch + off) = pack_hi2(v0, v1);
            *(uint32_t*)(g_Cl + off) = pack_lo2(v0, v1);
        }
    }
}

// ---------------------------------------------------------------------------
// Launch
// ---------------------------------------------------------------------------
extern "C" void kernel_launch(void* const* d_in, const int* in_sizes, int n_in,
                              void* d_out, int out_size)
{
    const float* input_q = (const float*)d_in[0];
    const float* input_k = (const float*)d_in[1];
    const float* input_v = (const float*)d_in[2];
    const int*   mask    = (const int*)  d_in[3];
    const float* Wq = (const float*)d_in[4];
    const float* bq = (const float*)d_in[5];
    const float* Wk = (const float*)d_in[6];
    const float* bk = (const float*)d_in[7];
    const float* Wv = (const float*)d_in[8];
    const float* bv = (const float*)d_in[9];
    const float* Wo = (const float*)d_in[10];
    const float* bo = (const float*)d_in[11];
    float* out = (float*)d_out;

    bf16 *ah, *al, *wh, *wl, *qh, *ql, *kh, *kl, *vh, *vl, *ch, *cl;
    cudaGetSymbolAddress((void**)&ah, g_Ah); cudaGetSymbolAddress((void**)&al, g_Al);
    cudaGetSymbolAddress((void**)&wh, g_Wh); cudaGetSymbolAddress((void**)&wl, g_Wl);
    cudaGetSymbolAddress((void**)&qh, g_Qh); cudaGetSymbolAddress((void**)&ql, g_Ql);
    cudaGetSymbolAddress((void**)&kh, g_Kh); cudaGetSymbolAddress((void**)&kl, g_Kl);
    cudaGetSymbolAddress((void**)&vh, g_Vh); cudaGetSymbolAddress((void**)&vl, g_Vl);
    cudaGetSymbolAddress((void**)&ch, g_Ch); cudaGetSymbolAddress((void**)&cl, g_Cl);

    cudaFuncSetAttribute(proj_mma,
                         cudaFuncAttributeMaxDynamicSharedMemorySize, PROJ_SMEM);
    cudaFuncSetAttribute(attn_mma,
                         cudaFuncAttributeMaxDynamicSharedMemorySize, ATTN_SMEM);

    const int N1Q = M_ * D_ / 4;   // input quads
    const int N2Q = D_ * D_ / 4;   // weight quads
    const int SPLIT_BLK = (N1Q + N2Q + 255) / 256;
    dim3 pgrid(D_ / 128, M_ / 128);   // (8, 32)
    dim3 agrid(S_ / 128, H_, B_);     // (16, 16, 2)

    // Q
    split_kernel<<<SPLIT_BLK, 256>>>((const float4*)input_q, (uint2*)ah, (uint2*)al, N1Q,
                                     (const float4*)Wq, (uint2*)wh, (uint2*)wl, N2Q);
    proj_mma<<<pgrid, 256, PROJ_SMEM>>>(ah, al, wh, wl, bq, nullptr, qh, ql, 1);
    // K
    split_kernel<<<SPLIT_BLK, 256>>>((const float4*)input_k, (uint2*)ah, (uint2*)al, N1Q,
                                     (const float4*)Wk, (uint2*)wh, (uint2*)wl, N2Q);
    proj_mma<<<pgrid, 256, PROJ_SMEM>>>(ah, al, wh, wl, bk, nullptr, kh, kl, 1);
    // V
    split_kernel<<<SPLIT_BLK, 256>>>((const float4*)input_v, (uint2*)ah, (uint2*)al, N1Q,
                                     (const float4*)Wv, (uint2*)wh, (uint2*)wl, N2Q);
    proj_mma<<<pgrid, 256, PROJ_SMEM>>>(ah, al, wh, wl, bv, nullptr, vh, vl, 1);
    // attention
    attn_mma<<<agrid, 256, ATTN_SMEM>>>(mask);
    // output projection
    split_kernel<<<(N2Q + 255) / 256, 256>>>((const float4*)Wo, (uint2*)wh, (uint2*)wl, N2Q,
                                             nullptr, nullptr, nullptr, 0);
    proj_mma<<<pgrid, 256, PROJ_SMEM>>>(ch, cl, wh, wl, bo, out, nullptr, nullptr, 0);
}

// round 13
// speedup vs baseline: 1.0033x; 1.0014x over previous
#include <cuda_runtime.h>
#include <cuda_bf16.h>
#include <cstdint>
#include <math.h>

// Problem constants
#define B_  2
#define S_  2048
#define D_  1024
#define H_  16
#define DK_ 64
#define M_  (B_*S_)   // 4096

typedef __nv_bfloat16 bf16;

// Scratch (allocation-free rule: __device__ globals), all hi/lo bf16 planes
__device__ bf16 g_Ah[(size_t)M_*D_], g_Al[(size_t)M_*D_];   // split input (reused q/k/v)
__device__ bf16 g_Wh[(size_t)D_*D_], g_Wl[(size_t)D_*D_];   // split weight (reused)
__device__ bf16 g_Qh[(size_t)M_*D_], g_Ql[(size_t)M_*D_];   // [B,H,S,DK]
__device__ bf16 g_Kh[(size_t)M_*D_], g_Kl[(size_t)M_*D_];
__device__ bf16 g_Vh[(size_t)M_*D_], g_Vl[(size_t)M_*D_];
__device__ bf16 g_Ch[(size_t)M_*D_], g_Cl[(size_t)M_*D_];   // context [B,S,D]

// ---------------------------------------------------------------------------
// Helpers
// ---------------------------------------------------------------------------
__device__ __forceinline__ void ldm_x4(uint32_t* r, uint32_t addr) {
    asm volatile("ldmatrix.sync.aligned.m8n8.x4.shared.b16 {%0,%1,%2,%3}, [%4];"
        : "=r"(r[0]), "=r"(r[1]), "=r"(r[2]), "=r"(r[3]) : "r"(addr));
}
__device__ __forceinline__ void ldm_x4_t(uint32_t* r, uint32_t addr) {
    asm volatile("ldmatrix.sync.aligned.m8n8.x4.trans.shared.b16 {%0,%1,%2,%3}, [%4];"
        : "=r"(r[0]), "=r"(r[1]), "=r"(r[2]), "=r"(r[3]) : "r"(addr));
}
__device__ __forceinline__ void mma_bf16(float* c, const uint32_t* a, const uint32_t* b) {
    asm volatile("mma.sync.aligned.m16n8k16.row.col.f32.bf16.bf16.f32 "
        "{%0,%1,%2,%3}, {%4,%5,%6,%7}, {%8,%9}, {%0,%1,%2,%3};"
        : "+f"(c[0]), "+f"(c[1]), "+f"(c[2]), "+f"(c[3])
        : "r"(a[0]), "r"(a[1]), "r"(a[2]), "r"(a[3]), "r"(b[0]), "r"(b[1]));
}
__device__ __forceinline__ uint32_t pack_hi2(float x, float y) {
    __nv_bfloat162 t(__float2bfloat16_rn(x), __float2bfloat16_rn(y));
    return *(uint32_t*)&t;
}
__device__ __forceinline__ uint32_t pack_lo2(float x, float y) {
    bf16 hx = __float2bfloat16_rn(x);
    bf16 hy = __float2bfloat16_rn(y);
    __nv_bfloat162 t(__float2bfloat16_rn(x - __bfloat162float(hx)),
                     __float2bfloat16_rn(y - __bfloat162float(hy)));
    return *(uint32_t*)&t;
}
__device__ __forceinline__ void cp16(uint32_t saddr, const void* g) {
    asm volatile("cp.async.cg.shared.global [%0], [%1], 16;" :: "r"(saddr), "l"(g));
}

// ---------------------------------------------------------------------------
// Split fp32 -> hi/lo bf16 planes (two arrays per launch)
// ---------------------------------------------------------------------------
__global__ void split_kernel(const float4* __restrict__ in1, uint2* __restrict__ h1,
                             uint2* __restrict__ l1, int n1q,
                             const float4* __restrict__ in2, uint2* __restrict__ h2,
                             uint2* __restrict__ l2, int n2q)
{
    int i = blockIdx.x * blockDim.x + threadIdx.x;
    const float4* in; uint2 *oh, *ol; int idx;
    if (i < n1q) { in = in1; oh = h1; ol = l1; idx = i; }
    else { idx = i - n1q; if (idx >= n2q) return; in = in2; oh = h2; ol = l2; }
    float4 v = in[idx];
    uint2 ph, pl;
    ph.x = pack_hi2(v.x, v.y); ph.y = pack_hi2(v.z, v.w);
    pl.x = pack_lo2(v.x, v.y); pl.y = pack_lo2(v.z, v.w);
    oh[idx] = ph; ol[idx] = pl;
}

// ---------------------------------------------------------------------------
// Pure-bf16 projection GEMM, cp.async double-buffered.
// out = A @ W^T + bias  (A = Ah+Al, W = Wh+Wl, 3-MMA emulated fp32)
// CTA 128x128, BK=32, 8 warps (2x4, warp tile 64x32), 2 CTAs/SM.
// ---------------------------------------------------------------------------
#define LDK 40
#define PLB  (128 * LDK * 2)        // plane bytes
#define STGB (4 * PLB)              // stage bytes (Ah,Al,Wh,Wl)
#define PROJ_SMEM (2 * STGB)        // 81,920 B

__global__ __launch_bounds__(256, 2) void proj_mma(
    const bf16* __restrict__ Ah, const bf16* __restrict__ Al,
    const bf16* __restrict__ Wh, const bf16* __restrict__ Wl,
    const float* __restrict__ bias,
    float* __restrict__ outF, bf16* __restrict__ outH, bf16* __restrict__ outL,
    int headSplit)
{
    extern __shared__ char smem_raw[];
    uint32_t smem_b = (uint32_t)__cvta_generic_to_shared(smem_raw);

    const int tid  = threadIdx.x;
    const int lane = tid & 31;
    const int wrp  = tid >> 5;
    const int wr = wrp >> 2;
    const int wc = wrp & 3;
    const int bm = blockIdx.y * 128;
    const int bn = blockIdx.x * 128;

    const int lrow = tid >> 1;
    const int lseg = (tid & 1) * 16;
    const bf16* gAh = Ah + (size_t)(bm + lrow) * D_ + lseg;
    const bf16* gAl = Al + (size_t)(bm + lrow) * D_ + lseg;
    const bf16* gWh = Wh + (size_t)(bn + lrow) * D_ + lseg;
    const bf16* gWl = Wl + (size_t)(bn + lrow) * D_ + lseg;
    const uint32_t sdst = smem_b + (uint32_t)(lrow * LDK + lseg) * 2u;

    float acc[4][4][4];
    #pragma unroll
    for (int mt = 0; mt < 4; mt++)
        #pragma unroll
        for (int nt = 0; nt < 4; nt++)
            #pragma unroll
            for (int r = 0; r < 4; r++) acc[mt][nt][r] = 0.f;

    const int a_r = lane & 15;
    const int a_k = (lane >> 4) * 8;
    const int b_r = (lane & 7) + ((lane >> 4) << 3);
    const int b_k = ((lane >> 3) & 1) * 8;

    // issue loads for a stage
    auto issue = [&](int stage, int k0) {
        uint32_t sb = sdst + stage * STGB;
        cp16(sb,               gAh + k0);
        cp16(sb + 16,          gAh + k0 + 8);
        cp16(sb + PLB,         gAl + k0);
        cp16(sb + PLB + 16,    gAl + k0 + 8);
        cp16(sb + 2*PLB,       gWh + k0);
        cp16(sb + 2*PLB + 16,  gWh + k0 + 8);
        cp16(sb + 3*PLB,       gWl + k0);
        cp16(sb + 3*PLB + 16,  gWl + k0 + 8);
        asm volatile("cp.async.commit_group;");
    };

    issue(0, 0);

    for (int c = 0; c < D_ / 32; c++) {
        if (c < D_ / 32 - 1) issue((c + 1) & 1, (c + 1) * 32);
        if (c < D_ / 32 - 1) asm volatile("cp.async.wait_group 1;");
        else                 asm volatile("cp.async.wait_group 0;");
        __syncthreads();

        uint32_t sAh_b = smem_b + (c & 1) * STGB;
        uint32_t sAl_b = sAh_b + PLB;
        uint32_t sWh_b = sAh_b + 2 * PLB;
        uint32_t sWl_b = sAh_b + 3 * PLB;

        #pragma unroll
        for (int ks = 0; ks < 2; ks++) {
            const int k0 = ks * 16;
            uint32_t afh[4][4], afl[4][4];
            #pragma unroll
            for (int mt = 0; mt < 4; mt++) {
                int m0 = wr * 64 + mt * 16;
                uint32_t off = (uint32_t)((m0 + a_r) * LDK + k0 + a_k) * 2u;
                ldm_x4(afh[mt], sAh_b + off);
                ldm_x4(afl[mt], sAl_b + off);
            }
            uint32_t bfh[4][2], bfl[4][2];
            #pragma unroll
            for (int np = 0; np < 2; np++) {
                int n0 = wc * 32 + np * 16;
                uint32_t off = (uint32_t)((n0 + b_r) * LDK + k0 + b_k) * 2u;
                uint32_t th[4], tl[4];
                ldm_x4(th, sWh_b + off);
                ldm_x4(tl, sWl_b + off);
                bfh[2*np][0]   = th[0]; bfh[2*np][1]   = th[1];
                bfh[2*np+1][0] = th[2]; bfh[2*np+1][1] = th[3];
                bfl[2*np][0]   = tl[0]; bfl[2*np][1]   = tl[1];
                bfl[2*np+1][0] = tl[2]; bfl[2*np+1][1] = tl[3];
            }
            #pragma unroll
            for (int mt = 0; mt < 4; mt++)
                #pragma unroll
                for (int nt = 0; nt < 4; nt++) {
                    mma_bf16(acc[mt][nt], afh[mt], bfh[nt]);
                    mma_bf16(acc[mt][nt], afl[mt], bfh[nt]);
                    mma_bf16(acc[mt][nt], afh[mt], bfl[nt]);
                }
        }
        __syncthreads();
    }

    // Epilogue
    const int g  = lane >> 2;
    const int i4 = lane & 3;
    #pragma unroll
    for (int mt = 0; mt < 4; mt++) {
        #pragma unroll
        for (int nt = 0; nt < 4; nt++) {
            int m = bm + wr * 64 + mt * 16 + g;
            int n = bn + wc * 32 + nt * 8 + i4 * 2;
            float b0 = bias[n], b1 = bias[n + 1];
            #pragma unroll
            for (int hf = 0; hf < 2; hf++) {
                int mm = m + hf * 8;
                float v0 = acc[mt][nt][hf * 2 + 0] + b0;
                float v1 = acc[mt][nt][hf * 2 + 1] + b1;
                if (headSplit) {
                    int bb = mm >> 11;
                    int s  = mm & (S_ - 1);
                    int h  = n >> 6;
                    int dk = n & (DK_ - 1);
                    size_t off = ((size_t)((bb * H_ + h) * S_ + s)) * DK_ + dk;
                    *(uint32_t*)(outH + off) = pack_hi2(v0, v1);
                    *(uint32_t*)(outL + off) = pack_lo2(v0, v1);
                } else {
                    *(float2*)(outF + (size_t)mm * D_ + n) = make_float2(v0, v1);
                }
            }
        }
    }
}

// ---------------------------------------------------------------------------
// Flash-attention on tensor cores, all operands pre-split bf16.
// CTA: 128 q-rows per (b,h). 8 warps x 16 rows, warp-local softmax,
// P in registers (C-frag == A-frag). 82.9 KB SMEM, 2 CTAs/SM.
// ---------------------------------------------------------------------------
#define LQ 72
#define ATTN_SMEM ((128*LQ + 64*LQ + 64*LQ) * 2 * 2 + 128*LQ)   // 82,944 B

__global__ __launch_bounds__(256, 2) void attn_mma(const int* __restrict__ mask)
{
    extern __shared__ char smem_raw[];
    bf16* Qh = (bf16*)smem_raw;
    bf16* Ql = Qh + 128 * LQ;
    bf16* Kh = Ql + 128 * LQ;
    bf16* Kl = Kh + 64 * LQ;
    bf16* Vh = Kl + 64 * LQ;
    bf16* Vl = Vh + 64 * LQ;
    uint8_t* Ms = (uint8_t*)(Vl + 64 * LQ);

    const int tid  = threadIdx.x;
    const int lane = tid & 31;
    const int warp = tid >> 5;
    const int b = blockIdx.z, h = blockIdx.y;
    const int q0 = blockIdx.x * 128;

    const size_t bh = ((size_t)(b * H_ + h)) * S_ * DK_;
    const bf16* Qhg = g_Qh + bh; const bf16* Qlg = g_Ql + bh;
    const bf16* Khg = g_Kh + bh; const bf16* Klg = g_Kl + bh;
    const bf16* Vhg = g_Vh + bh; const bf16* Vlg = g_Vl + bh;
    const int*  mb  = mask + (size_t)b * S_ * S_;

    uint32_t Qh_b = (uint32_t)__cvta_generic_to_shared(Qh);
    uint32_t Ql_b = (uint32_t)__cvta_generic_to_shared(Ql);
    uint32_t Kh_b = (uint32_t)__cvta_generic_to_shared(Kh);
    uint32_t Kl_b = (uint32_t)__cvta_generic_to_shared(Kl);
    uint32_t Vh_b = (uint32_t)__cvta_generic_to_shared(Vh);
    uint32_t Vl_b = (uint32_t)__cvta_generic_to_shared(Vl);

    // Load Q tile (row = tid>>1, 32-col half) — straight bf16 copies
    {
        int row = tid >> 1, seg = (tid & 1) * 32;
        const uint4* sh = (const uint4*)(Qhg + (size_t)(q0 + row) * DK_ + seg);
        const uint4* sl = (const uint4*)(Qlg + (size_t)(q0 + row) * DK_ + seg);
        uint4* dh = (uint4*)(Qh + row * LQ + seg);
        uint4* dl = (uint4*)(Ql + row * LQ + seg);
        #pragma unroll
        for (int u = 0; u < 4; u++) { dh[u] = sh[u]; dl[u] = sl[u]; }
    }

    float m_i[2] = { -INFINITY, -INFINITY };
    float l_i[2] = { 0.f, 0.f };
    float o[8][4];
    #pragma unroll
    for (int nt = 0; nt < 8; nt++)
        #pragma unroll
        for (int r = 0; r < 4; r++) o[nt][r] = 0.f;

    const int a_r = lane & 15;
    const int a_k = (lane >> 4) * 8;
    const int b_r = (lane & 7) + ((lane >> 4) << 3);
    const int b_k = ((lane >> 3) & 1) * 8;
    const int t_r = (lane & 7) + (((lane >> 3) & 1) << 3);
    const int t_c = (lane >> 4) * 8;

    for (int k0 = 0; k0 < S_; k0 += 64) {
        __syncthreads();

        // K/V tile copy (row = tid>>2, 16-col quarter)
        {
            int row = tid >> 2, seg = (tid & 3) * 16;
            size_t go = (size_t)(k0 + row) * DK_ + seg;
            int so = row * LQ + seg;
            #pragma unroll
            for (int u = 0; u < 2; u++) {
                ((uint4*)(Kh + so))[u] = ((const uint4*)(Khg + go))[u];
                ((uint4*)(Kl + so))[u] = ((const uint4*)(Klg + go))[u];
                ((uint4*)(Vh + so))[u] = ((const uint4*)(Vhg + go))[u];
                ((uint4*)(Vl + so))[u] = ((const uint4*)(Vlg + go))[u];
            }
        }
        // mask tile -> bytes
        {
            int row = tid >> 1, seg = (tid & 1) * 32;
            const int* mrow = mb + (size_t)(q0 + row) * S_ + k0 + seg;
            #pragma unroll
            for (int u = 0; u < 8; u++) {
                int4 m4 = *(const int4*)(mrow + u * 4);
                uchar4 cc;
                cc.x = (unsigned char)m4.x; cc.y = (unsigned char)m4.y;
                cc.z = (unsigned char)m4.z; cc.w = (unsigned char)m4.w;
                *(uchar4*)(Ms + row * LQ + seg + u * 4) = cc;
            }
        }
        __syncthreads();

        // ---- S = Q @ K^T ----
        float s[8][4];
        #pragma unroll
        for (int nt = 0; nt < 8; nt++)
            #pragma unroll
            for (int r = 0; r < 4; r++) s[nt][r] = 0.f;

        #pragma unroll
        for (int kt = 0; kt < 4; kt++) {
            uint32_t ah[4], al[4];
            uint32_t aoff = (uint32_t)((warp * 16 + a_r) * LQ + kt * 16 + a_k) * 2u;
            ldm_x4(ah, Qh_b + aoff);
            ldm_x4(al, Ql_b + aoff);
            #pragma unroll
            for (int nc = 0; nc < 4; nc++) {
                uint32_t bhf[4], blf[4];
                uint32_t boff = (uint32_t)((nc * 16 + b_r) * LQ + kt * 16 + b_k) * 2u;
                ldm_x4(bhf, Kh_b + boff);
                ldm_x4(blf, Kl_b + boff);
                mma_bf16(s[2*nc],   ah, &bhf[0]);
                mma_bf16(s[2*nc],   al, &bhf[0]);
                mma_bf16(s[2*nc],   ah, &blf[0]);
                mma_bf16(s[2*nc+1], ah, &bhf[2]);
                mma_bf16(s[2*nc+1], al, &bhf[2]);
                mma_bf16(s[2*nc+1], ah, &blf[2]);
            }
        }

        // ---- mask + online softmax ----
        const int grow0 = warp * 16 + (lane >> 2);
        const int cb = (lane & 3) * 2;
        #pragma unroll
        for (int r = 0; r < 2; r++) {
            int grow = grow0 + r * 8;
            float tmax = -INFINITY;
            #pragma unroll
            for (int nt = 0; nt < 8; nt++) {
                uint8_t mk0 = Ms[grow * LQ + nt * 8 + cb];
                uint8_t mk1 = Ms[grow * LQ + nt * 8 + cb + 1];
                float v0 = mk0 ? s[nt][r*2+0] * 0.125f : -1e9f;
                float v1 = mk1 ? s[nt][r*2+1] * 0.125f : -1e9f;
                s[nt][r*2+0] = v0; s[nt][r*2+1] = v1;
                tmax = fmaxf(tmax, fmaxf(v0, v1));
            }
            tmax = fmaxf(tmax, __shfl_xor_sync(0xffffffffu, tmax, 1));
            tmax = fmaxf(tmax, __shfl_xor_sync(0xffffffffu, tmax, 2));
            float mnew = fmaxf(m_i[r], tmax);
            float esc = __expf(m_i[r] - mnew);
            float rs = 0.f;
            #pragma unroll
            for (int nt = 0; nt < 8; nt++) {
                float p0 = __expf(s[nt][r*2+0] - mnew);
                float p1 = __expf(s[nt][r*2+1] - mnew);
                s[nt][r*2+0] = p0; s[nt][r*2+1] = p1;
                rs += p0 + p1;
            }
            rs += __shfl_xor_sync(0xffffffffu, rs, 1);
            rs += __shfl_xor_sync(0xffffffffu, rs, 2);
            l_i[r] = l_i[r] * esc + rs;
            m_i[r] = mnew;
            #pragma unroll
            for (int nt = 0; nt < 8; nt++) {
                o[nt][r*2+0] *= esc;
                o[nt][r*2+1] *= esc;
            }
        }

        // P C-frag -> A-frag packs (hi/lo)
        uint32_t pfh[4][4], pfl[4][4];
        #pragma unroll
        for (int kt = 0; kt < 4; kt++) {
            pfh[kt][0] = pack_hi2(s[2*kt][0],   s[2*kt][1]);
            pfh[kt][1] = pack_hi2(s[2*kt][2],   s[2*kt][3]);
            pfh[kt][2] = pack_hi2(s[2*kt+1][0], s[2*kt+1][1]);
            pfh[kt][3] = pack_hi2(s[2*kt+1][2], s[2*kt+1][3]);
            pfl[kt][0] = pack_lo2(s[2*kt][0],   s[2*kt][1]);
            pfl[kt][1] = pack_lo2(s[2*kt][2],   s[2*kt][3]);
            pfl[kt][2] = pack_lo2(s[2*kt+1][0], s[2*kt+1][1]);
            pfl[kt][3] = pack_lo2(s[2*kt+1][2], s[2*kt+1][3]);
        }

        // ---- O += P @ V ----
        #pragma unroll
        for (int kt = 0; kt < 4; kt++) {
            #pragma unroll
            for (int nd = 0; nd < 4; nd++) {
                uint32_t vh_[4], vl_[4];
                uint32_t voff = (uint32_t)((kt * 16 + t_r) * LQ + nd * 16 + t_c) * 2u;
                ldm_x4_t(vh_, Vh_b + voff);
                ldm_x4_t(vl_, Vl_b + voff);
                mma_bf16(o[2*nd],   pfh[kt], &vh_[0]);
                mma_bf16(o[2*nd],   pfl[kt], &vh_[0]);
                mma_bf16(o[2*nd],   pfh[kt], &vl_[0]);
                mma_bf16(o[2*nd+1], pfh[kt], &vh_[2]);
                mma_bf16(o[2*nd+1], pfl[kt], &vh_[2]);
                mma_bf16(o[2*nd+1], pfh[kt], &vl_[2]);
            }
        }
    }

    // Epilogue: normalize, write context hi/lo bf16 planes [B,S,D]
    #pragma unroll
    for (int r = 0; r < 2; r++) {
        int q = q0 + warp * 16 + (lane >> 2) + r * 8;
        float inv = 1.f / l_i[r];
        #pragma unroll
        for (int nt = 0; nt < 8; nt++) {
            float v0 = o[nt][r*2+0] * inv;
            float v1 = o[nt][r*2+1] * inv;
            size_t off = ((size_t)(b * S_ + q)) * D_ + h * DK_ + nt * 8 + (lane & 3) * 2;
            *(uint32_t*)(g_Ch + off) = pack_hi2(v0, v1);
            *(uint32_t*)(g_Cl + off) = pack_lo2(v0, v1);
        }
    }
}

// ---------------------------------------------------------------------------
// Launch
// ---------------------------------------------------------------------------
extern "C" void kernel_launch(void* const* d_in, const int* in_sizes, int n_in,
                              void* d_out, int out_size)
{
    const float* input_q = (const float*)d_in[0];
    const float* input_k = (const float*)d_in[1];
    const float* input_v = (const float*)d_in[2];
    const int*   mask    = (const int*)  d_in[3];
    const float* Wq = (const float*)d_in[4];
    const float* bq = (const float*)d_in[5];
    const float* Wk = (const float*)d_in[6];
    const float* bk = (const float*)d_in[7];
    const float* Wv = (const float*)d_in[8];
    const float* bv = (const float*)d_in[9];
    const float* Wo = (const float*)d_in[10];
    const float* bo = (const float*)d_in[11];
    float* out = (float*)d_out;

    bf16 *ah, *al, *wh, *wl, *qh, *ql, *kh, *kl, *vh, *vl, *ch, *cl;
    cudaGetSymbolAddress((void**)&ah, g_Ah); cudaGetSymbolAddress((void**)&al, g_Al);
    cudaGetSymbolAddress((void**)&wh, g_Wh); cudaGetSymbolAddress((void**)&wl, g_Wl);
    cudaGetSymbolAddress((void**)&qh, g_Qh); cudaGetSymbolAddress((void**)&ql, g_Ql);
    cudaGetSymbolAddress((void**)&kh, g_Kh); cudaGetSymbolAddress((void**)&kl, g_Kl);
    cudaGetSymbolAddress((void**)&vh, g_Vh); cudaGetSymbolAddress((void**)&vl, g_Vl);
    cudaGetSymbolAddress((void**)&ch, g_Ch); cudaGetSymbolAddress((void**)&cl, g_Cl);

    cudaFuncSetAttribute(proj_mma,
                         cudaFuncAttributeMaxDynamicSharedMemorySize, PROJ_SMEM);
    cudaFuncSetAttribute(attn_mma,
                         cudaFuncAttributeMaxDynamicSharedMemorySize, ATTN_SMEM);

    const int N1Q = M_ * D_ / 4;   // input quads
    const int N2Q = D_ * D_ / 4;   // weight quads
    const int SPLIT_BLK = (N1Q + N2Q + 255) / 256;
    dim3 pgrid(D_ / 128, M_ / 128);   // (8, 32)
    dim3 agrid(S_ / 128, H_, B_);     // (16, 16, 2)

    // Q
    split_kernel<<<SPLIT_BLK, 256>>>((const float4*)input_q, (uint2*)ah, (uint2*)al, N1Q,
                                     (const float4*)Wq, (uint2*)wh, (uint2*)wl, N2Q);
    proj_mma<<<pgrid, 256, PROJ_SMEM>>>(ah, al, wh, wl, bq, nullptr, qh, ql, 1);
    // K
    split_kernel<<<SPLIT_BLK, 256>>>((const float4*)input_k, (uint2*)ah, (uint2*)al, N1Q,
                                     (const float4*)Wk, (uint2*)wh, (uint2*)wl, N2Q);
    proj_mma<<<pgrid, 256, PROJ_SMEM>>>(ah, al, wh, wl, bk, nullptr, kh, kl, 1);
    // V
    split_kernel<<<SPLIT_BLK, 256>>>((const float4*)input_v, (uint2*)ah, (uint2*)al, N1Q,
                                     (const float4*)Wv, (uint2*)wh, (uint2*)wl, N2Q);
    proj_mma<<<pgrid, 256, PROJ_SMEM>>>(ah, al, wh, wl, bv, nullptr, vh, vl, 1);
    // attention
    attn_mma<<<agrid, 256, ATTN_SMEM>>>(mask);
    // output projection
    split_kernel<<<(N2Q + 255) / 256, 256>>>((const float4*)Wo, (uint2*)wh, (uint2*)wl, N2Q,
                                             nullptr, nullptr, nullptr, 0);
    proj_mma<<<pgrid, 256, PROJ_SMEM>>>(ch, cl, wh, wl, bo, out, nullptr, nullptr, 0);
}